// round 11
// baseline (speedup 1.0000x reference)
#include <cuda_runtime.h>
#include <cuda_fp16.h>
#include <cstdint>

// Problem constants
constexpr int Bn  = 4;
constexpr int Sn  = 2048;
constexpr int Dn  = 1024;
constexpr int Hn  = 16;
constexpr int HDn = 64;
constexpr int MRn = Bn * Sn;

constexpr unsigned SMEM_BYTES = 147456 + 256;  // gemm: 3 x (16KB A + 32KB B)
constexpr unsigned FLASH_SMEM = 81920 + 256;   // flash: Q 32KB + K 3x8KB + Vt 3x8KB

// Scratch (device globals; 16B-aligned for cp.async)
__device__ __align__(256) __half g_Q[(size_t)Bn * Hn * Sn * HDn];   // [b,h,s,hd] (scaled log2e/8)
__device__ __align__(256) __half g_K[(size_t)Bn * Hn * Sn * HDn];
__device__ __align__(256) __half g_Vt[(size_t)Bn * Hn * HDn * Sn];  // [b,h,hd,s]
__device__ __align__(256) __half g_ctx[(size_t)MRn * Dn];           // [b,s,d]
__device__ __align__(256) __half g_x[(size_t)MRn * Dn];             // half copy of x
__device__ __align__(256) __half g_Wt[(size_t)4 * Dn * Dn];         // [z][n][k] transposed

// ---------------------------------------------------------------------------
// Helpers
// ---------------------------------------------------------------------------
__device__ __forceinline__ uint32_t smem_u32(const void* p) {
    uint32_t a;
    asm("{ .reg .u64 t; cvta.to.shared.u64 t, %1; cvt.u32.u64 %0, t; }" : "=r"(a) : "l"(p));
    return a;
}
__device__ __forceinline__ void cp16(uint32_t dst, const void* src) {
    asm volatile("cp.async.cg.shared.global [%0], [%1], 16;" :: "r"(dst), "l"(src) : "memory");
}
#define CP_COMMIT() asm volatile("cp.async.commit_group;" ::: "memory")
#define CP_WAIT1()  asm volatile("cp.async.wait_group 1;"  ::: "memory")

__device__ __forceinline__ void ldmx4(uint32_t* r, uint32_t a) {
    asm volatile("ldmatrix.sync.aligned.m8n8.x4.shared.b16 {%0,%1,%2,%3}, [%4];"
                 : "=r"(r[0]), "=r"(r[1]), "=r"(r[2]), "=r"(r[3]) : "r"(a));
}
__device__ __forceinline__ uint32_t pack_h2(float lo, float hi) {
    __half2 h = __floats2half2_rn(lo, hi);
    return *reinterpret_cast<uint32_t*>(&h);
}
__device__ __forceinline__ uint32_t ex2h2(uint32_t x) {
    uint32_t r;
    asm("ex2.approx.f16x2 %0, %1;" : "=r"(r) : "r"(x));
    return r;
}

// mma.sync m16n8k16 fp16 -> f32 accum: D = A@B + D (A row-major, B col-major)
__device__ __forceinline__ void mma_f16(float* c, const uint32_t* a, const uint32_t* b) {
    asm volatile(
        "mma.sync.aligned.m16n8k16.row.col.f32.f16.f16.f32 "
        "{%0,%1,%2,%3}, {%4,%5,%6,%7}, {%8,%9}, {%0,%1,%2,%3};"
        : "+f"(c[0]), "+f"(c[1]), "+f"(c[2]), "+f"(c[3])
        : "r"(a[0]), "r"(a[1]), "r"(a[2]), "r"(a[3]), "r"(b[0]), "r"(b[1]));
}

// ---------------------------------------------------------------------------
// Prepass 1: x (fp32) -> g_x (fp16 RN)
// ---------------------------------------------------------------------------
__global__ __launch_bounds__(256) void round_x_kernel(const float4* __restrict__ x) {
    size_t n4 = (size_t)MRn * Dn / 4;
    for (size_t i = (size_t)blockIdx.x * blockDim.x + threadIdx.x; i < n4;
         i += (size_t)gridDim.x * blockDim.x) {
        float4 v = x[i];
        reinterpret_cast<uint2*>(g_x)[i] =
            make_uint2(pack_h2(v.x, v.y), pack_h2(v.z, v.w));
    }
}

// ---------------------------------------------------------------------------
// Prepass 2: transpose + round weights: g_Wt[z][n][k] = half(W_z[k][n])
// ---------------------------------------------------------------------------
__global__ __launch_bounds__(256) void transpose_w_kernel(
    const float* __restrict__ w0, const float* __restrict__ w1,
    const float* __restrict__ w2, const float* __restrict__ w3)
{
    __shared__ float tile[32][33];
    int z = blockIdx.z;
    const float* w = (z == 0) ? w0 : (z == 1) ? w1 : (z == 2) ? w2 : w3;
    __half* wt = g_Wt + (size_t)z * Dn * Dn;

    int tx = threadIdx.x, ty = threadIdx.y;
    int n = blockIdx.x * 32 + tx;
    int k0 = blockIdx.y * 32;
#pragma unroll
    for (int j = 0; j < 32; j += 8)
        tile[ty + j][tx] = w[(size_t)(k0 + ty + j) * Dn + n];
    __syncthreads();
    int ko = k0 + tx;
    int no = blockIdx.x * 32 + ty;
#pragma unroll
    for (int j = 0; j < 32; j += 8)
        wt[(size_t)(no + j) * Dn + ko] = __float2half_rn(tile[tx][ty + j]);
}

// ---------------------------------------------------------------------------
// fp16 mma.sync GEMM — BM=128, BN=256, warp tile 64x64 (2Mx4N warps).
// Fragment bytes/MAC at the smem-crossbar balance point. 3-stage cp.async,
// one sync per kt, BK=64 halves (128B rows, XOR swizzle).
// MODE 0: A=g_x, z in {0,1}: wq -> g_Q (scaled log2e/8), wk -> g_K
// MODE 1: A=g_ctx, W=wo (slot 3) -> Cout fp32 flat
// MODE 2: A=g_Wt slot2 (M=1024), B=g_x (N=8192) -> g_Vt [d][s] coalesced
// ---------------------------------------------------------------------------
template <int MODE>
__global__ __launch_bounds__(256)
void mma_gemm(float* __restrict__ Cout)
{
    extern __shared__ char smem[];
    const uint32_t sbuf = (smem_u32(smem) + 127u) & ~127u;

    const int tid  = threadIdx.x;
    const int wid  = tid >> 5;
    const int lane = tid & 31;
    const int g    = lane >> 2;
    const int t    = lane & 3;
    const int wm   = wid & 1;
    const int wn   = wid >> 1;

    const int n0 = blockIdx.x * 256;
    const int m0 = blockIdx.y * 128;
    const int z  = (MODE == 0) ? blockIdx.z : 3;

    const __half* __restrict__ A =
        (MODE == 0) ? g_x : (MODE == 2) ? (g_Wt + (size_t)2 * Dn * Dn) : g_ctx;
    const __half* __restrict__ Bt =
        (MODE == 2) ? g_x : (g_Wt + (size_t)z * Dn * Dn);

    auto load_tiles = [&](int kt, int bufi) {
        const uint32_t dst = sbuf + (uint32_t)bufi * 49152u;
        const int k0 = kt * 64;
#pragma unroll
        for (int i = 0; i < 4; i++) {          // A: 128 rows
            int c  = tid + i * 256;
            int r  = c >> 3;
            int kc = c & 7;
            uint32_t off = (uint32_t)(r * 128) + (uint32_t)((kc ^ (r & 7)) << 4);
            cp16(dst + off, A + (size_t)(m0 + r) * Dn + k0 + kc * 8);
        }
#pragma unroll
        for (int i = 0; i < 8; i++) {          // B: 256 rows
            int c  = tid + i * 256;
            int r  = c >> 3;
            int kc = c & 7;
            uint32_t off = (uint32_t)(r * 128) + (uint32_t)((kc ^ (r & 7)) << 4);
            cp16(dst + 16384u + off, Bt + (size_t)(n0 + r) * Dn + k0 + kc * 8);
        }
    };

    load_tiles(0, 0); CP_COMMIT();
    load_tiles(1, 1); CP_COMMIT();

    float acc[4][8][4];
#pragma unroll
    for (int i = 0; i < 4; i++)
#pragma unroll
        for (int j = 0; j < 8; j++)
#pragma unroll
            for (int r = 0; r < 4; r++) acc[i][j][r] = 0.f;

    // Per-lane ldmatrix address components
    const uint32_t aRowL = (uint32_t)(wm * 64 + (lane & 15));    // + i*16
    const uint32_t aSw   = aRowL & 7u;
    const uint32_t aCs   = (uint32_t)(lane >> 4);
    const uint32_t bRowL = (uint32_t)(wn * 64 + (lane & 7));     // + (p*2 + bJ)*8
    const uint32_t bSw   = bRowL & 7u;
    const uint32_t bCs   = (uint32_t)((lane >> 3) & 1);
    const uint32_t bJ    = (uint32_t)(lane >> 4);

    for (int kt = 0; kt < 16; kt++) {      // Dn / 64
        CP_WAIT1();
        __syncthreads();
        if (kt + 2 < 16) load_tiles(kt + 2, (kt + 2) % 3);
        CP_COMMIT();

        const uint32_t aB = sbuf + (uint32_t)(kt % 3) * 49152u;
        const uint32_t bB = aB + 16384u;

#pragma unroll
        for (int ks = 0; ks < 4; ks++) {   // 4 x k16
            uint32_t afr[4][4];
#pragma unroll
            for (int i = 0; i < 4; i++)
                ldmx4(afr[i], aB + (aRowL + (uint32_t)(i * 16)) * 128u
                                 + ((((uint32_t)(2 * ks) + aCs) ^ aSw) << 4));
            uint32_t bfr[8][2];
#pragma unroll
            for (int p = 0; p < 4; p++) {
                uint32_t tmp[4];
                ldmx4(tmp, bB + (bRowL + ((uint32_t)(p * 2) + bJ) * 8u) * 128u
                             + ((((uint32_t)(2 * ks) + bCs) ^ bSw) << 4));
                bfr[p * 2][0]     = tmp[0]; bfr[p * 2][1]     = tmp[1];
                bfr[p * 2 + 1][0] = tmp[2]; bfr[p * 2 + 1][1] = tmp[3];
            }
#pragma unroll
            for (int i = 0; i < 4; i++)
#pragma unroll
                for (int j = 0; j < 8; j++)
                    mma_f16(acc[i][j], afr[i], bfr[j]);
        }
    }

    // --------------------------- Epilogue ---------------------------
    if (MODE == 2) {
        // rows = d-dim (h,hd), cols = m-dim (b,s): coalesced packed writes
#pragma unroll
        for (int i = 0; i < 4; i++) {
            const int row0 = m0 + wm * 64 + i * 16 + g;
#pragma unroll
            for (int j = 0; j < 8; j++) {
                const int col = n0 + wn * 64 + j * 8 + 2 * t;   // m index (s even)
                const int b   = col >> 11;
                const int s   = col & 2047;
#pragma unroll
                for (int half = 0; half < 2; half++) {
                    const int d  = row0 + half * 8;
                    const int h  = d >> 6;
                    const int hd = d & 63;
                    *reinterpret_cast<uint32_t*>(
                        g_Vt + ((size_t)((b * Hn + h) * HDn + hd)) * Sn + s) =
                        pack_h2(acc[i][j][half * 2], acc[i][j][half * 2 + 1]);
                }
            }
        }
    } else if (MODE == 0) {
        __half* outq = (z == 0) ? g_Q : g_K;
        const float sc = (z == 0) ? 0.18033688011112042f : 1.0f;  // log2e/8
#pragma unroll
        for (int i = 0; i < 4; i++) {
            const int row0 = m0 + wm * 64 + i * 16 + g;
#pragma unroll
            for (int j = 0; j < 8; j++) {
                const int col = n0 + wn * 64 + j * 8 + 2 * t;
                const int h   = col >> 6;
                const int hd  = col & 63;
#pragma unroll
                for (int half = 0; half < 2; half++) {
                    const int row = row0 + half * 8;
                    const int b   = row >> 11;
                    const int s   = row & 2047;
                    *reinterpret_cast<uint32_t*>(
                        outq + ((size_t)((b * Hn + h) * Sn + s)) * HDn + hd) =
                        pack_h2(acc[i][j][half * 2] * sc, acc[i][j][half * 2 + 1] * sc);
                }
            }
        }
    } else {
#pragma unroll
        for (int i = 0; i < 4; i++) {
            const int row0 = m0 + wm * 64 + i * 16 + g;
#pragma unroll
            for (int j = 0; j < 8; j++) {
                const int col = n0 + wn * 64 + j * 8 + 2 * t;
#pragma unroll
                for (int half = 0; half < 2; half++) {
                    const int row = row0 + half * 8;
                    *reinterpret_cast<float2*>(Cout + (size_t)row * Dn + col) =
                        make_float2(acc[i][j][half * 2], acc[i][j][half * 2 + 1]);
                }
            }
        }
    }
}

// ---------------------------------------------------------------------------
// Tensor-core flash attention (causal), fp16 MMA, no-max softmax.
// Block: 256 queries x (b,h). 8 warps, warp = 32 q-rows (two m16 bands) x 64
// keys -> each K/V fragment read feeds 2x the MMAs (crossbar rebalance).
// p = ex2.f16x2 on packed scores (Q pre-scaled by log2e/8); masked -> 0.
// Row-sums via ones-column MMA. 3-stage cp.async, one sync per key tile.
// ---------------------------------------------------------------------------
__global__ __launch_bounds__(256)
void flash_mma()
{
    extern __shared__ char fsm[];
    const uint32_t sb = (smem_u32(fsm) + 127u) & ~127u;
    const uint32_t Qb = sb;            // 32KB (256 x 64 halves)
    const uint32_t Kb = sb + 32768u;   // 3 x 8KB
    const uint32_t Vb = sb + 57344u;   // 3 x 8KB

    const int qt = (int)gridDim.x - 1 - (int)blockIdx.x;   // heavy tiles first
    const int bh = blockIdx.y;
    const int q0 = qt * 256;

    const __half* __restrict__ Qg  = g_Q  + (size_t)bh * Sn * HDn;
    const __half* __restrict__ Kg  = g_K  + (size_t)bh * Sn * HDn;
    const __half* __restrict__ Vtg = g_Vt + (size_t)bh * HDn * Sn;

    const int tid  = threadIdx.x;
    const int w    = tid >> 5;
    const int lane = tid & 31;
    const int g    = lane >> 2;
    const int t    = lane & 3;

    auto loadKV = [&](int kt, int bufi) {
        const int k0 = kt * 64;
        const uint32_t kb = Kb + (uint32_t)bufi * 8192u;
        const uint32_t vb = Vb + (uint32_t)bufi * 8192u;
#pragma unroll
        for (int i = 0; i < 2; i++) {
            int lin = tid + i * 256;
            int r = lin >> 3, kc = lin & 7;
            uint32_t off = (uint32_t)(r * 128) + (uint32_t)((kc ^ (r & 7)) << 4);
            cp16(kb + off, Kg  + (size_t)(k0 + r) * HDn + kc * 8);
            cp16(vb + off, Vtg + (size_t)r * Sn + k0 + kc * 8);
        }
    };

    // Prologue: group 0 = Q tile (256 rows) + KV(0); group 1 = KV(1)
#pragma unroll
    for (int i = 0; i < 8; i++) {
        int lin = tid + i * 256;
        int r = lin >> 3, kc = lin & 7;
        uint32_t dst = Qb + (uint32_t)(r * 128) + (uint32_t)((kc ^ (r & 7)) << 4);
        cp16(dst, Qg + (size_t)(q0 + r) * HDn + kc * 8);
    }
    loadKV(0, 0); CP_COMMIT();
    loadKV(1, 1); CP_COMMIT();

    float O0[8][4], O1[8][4];
#pragma unroll
    for (int j = 0; j < 8; j++)
#pragma unroll
        for (int r = 0; r < 4; r++) { O0[j][r] = 0.f; O1[j][r] = 0.f; }
    float lacc0[4] = {0.f, 0.f, 0.f, 0.f};
    float lacc1[4] = {0.f, 0.f, 0.f, 0.f};

    uint32_t qa0[4][4], qa1[4][4];
    const int nk = 4 * (qt + 1);

    // Ones-column B fragment (B[k][0] = 1, else 0)
    const uint32_t bones = (lane < 4) ? 0x3C003C00u : 0u;
    const uint32_t bz[2] = {bones, bones};

    // Per-lane ldmatrix address components
    const uint32_t aRowL = (uint32_t)(w * 32 + (lane & 15));     // band0; band1 +16
    const uint32_t aSw0  = aRowL & 7u;
    const uint32_t aCs   = (uint32_t)(lane >> 4);
    const uint32_t bRowL = (uint32_t)((lane & 7) + (lane >> 4) * 8);  // + p*16
    const uint32_t bSw   = (uint32_t)(lane & 7);
    const uint32_t bCs   = (uint32_t)((lane >> 3) & 1);

    for (int kt = 0; kt < nk; kt++) {
        CP_WAIT1();
        __syncthreads();
        if (kt + 2 < nk) loadKV(kt + 2, (kt + 2) % 3);
        CP_COMMIT();

        if (kt == 0) {   // preload Q fragments for both bands
#pragma unroll
            for (int ks = 0; ks < 4; ks++) {
                uint32_t csw = (((uint32_t)(2 * ks) + aCs) ^ aSw0) << 4;
                ldmx4(qa0[ks], Qb + aRowL * 128u + csw);
                ldmx4(qa1[ks], Qb + (aRowL + 16u) * 128u + csw);
            }
        }

        const int k0 = kt * 64;
        const uint32_t kb = Kb + (uint32_t)(kt % 3) * 8192u;
        const uint32_t vb = Vb + (uint32_t)(kt % 3) * 8192u;

        // ---- S = Q @ K^T, both bands share each K fragment ----
        float S0[8][4], S1[8][4];
#pragma unroll
        for (int j = 0; j < 8; j++)
#pragma unroll
            for (int r = 0; r < 4; r++) { S0[j][r] = 0.f; S1[j][r] = 0.f; }

#pragma unroll
        for (int ks = 0; ks < 4; ks++) {
            const uint32_t csw = (((uint32_t)(2 * ks) + bCs) ^ bSw) << 4;
#pragma unroll
            for (int p = 0; p < 4; p++) {
                uint32_t tmp[4];
                ldmx4(tmp, kb + (bRowL + (uint32_t)(p * 16)) * 128u + csw);
                mma_f16(S0[p * 2],     qa0[ks], tmp);
                mma_f16(S0[p * 2 + 1], qa0[ks], tmp + 2);
                mma_f16(S1[p * 2],     qa1[ks], tmp);
                mma_f16(S1[p * 2 + 1], qa1[ks], tmp + 2);
            }
        }

        // ---- causal mask (tiles overlapping the block diagonal) ----
        const int qb0 = q0 + w * 32 + g;        // band0 rows qb0, qb0+8
        const int qb1 = qb0 + 16;               // band1 rows qb1, qb1+8
        if ((k0 + 63) > qb0) {
#pragma unroll
            for (int j = 0; j < 8; j++) {
                const int key0 = k0 + j * 8 + 2 * t;
                const int key1 = key0 + 1;
                if (key0 > qb0)     S0[j][0] = -1e30f;
                if (key1 > qb0)     S0[j][1] = -1e30f;
                if (key0 > qb0 + 8) S0[j][2] = -1e30f;
                if (key1 > qb0 + 8) S0[j][3] = -1e30f;
                if (key0 > qb1)     S1[j][0] = -1e30f;
                if (key1 > qb1)     S1[j][1] = -1e30f;
                if (key0 > qb1 + 8) S1[j][2] = -1e30f;
                if (key1 > qb1 + 8) S1[j][3] = -1e30f;
            }
        }

        // ---- p = 2^S in f16x2; ctx += P @ V (V frag shared); l += P @ ones ----
#pragma unroll
        for (int ks = 0; ks < 4; ks++) {
            uint32_t a0[4] = {
                ex2h2(pack_h2(S0[2 * ks][0],     S0[2 * ks][1])),
                ex2h2(pack_h2(S0[2 * ks][2],     S0[2 * ks][3])),
                ex2h2(pack_h2(S0[2 * ks + 1][0], S0[2 * ks + 1][1])),
                ex2h2(pack_h2(S0[2 * ks + 1][2], S0[2 * ks + 1][3])) };
            uint32_t a1[4] = {
                ex2h2(pack_h2(S1[2 * ks][0],     S1[2 * ks][1])),
                ex2h2(pack_h2(S1[2 * ks][2],     S1[2 * ks][3])),
                ex2h2(pack_h2(S1[2 * ks + 1][0], S1[2 * ks + 1][1])),
                ex2h2(pack_h2(S1[2 * ks + 1][2], S1[2 * ks + 1][3])) };

            mma_f16(lacc0, a0, bz);
            mma_f16(lacc1, a1, bz);

            const uint32_t csw = (((uint32_t)(2 * ks) + bCs) ^ bSw) << 4;
#pragma unroll
            for (int p = 0; p < 4; p++) {
                uint32_t tmp[4];
                ldmx4(tmp, vb + (bRowL + (uint32_t)(p * 16)) * 128u + csw);
                mma_f16(O0[p * 2],     a0, tmp);
                mma_f16(O0[p * 2 + 1], a0, tmp + 2);
                mma_f16(O1[p * 2],     a1, tmp);
                mma_f16(O1[p * 2 + 1], a1, tmp + 2);
            }
        }
    }

    // ---- epilogue: broadcast l (col 0, lanes t==0), then ctx/l ----
    const float l00 = __shfl_sync(0xffffffffu, lacc0[0], lane & 28);
    const float l01 = __shfl_sync(0xffffffffu, lacc0[2], lane & 28);
    const float l10 = __shfl_sync(0xffffffffu, lacc1[0], lane & 28);
    const float l11 = __shfl_sync(0xffffffffu, lacc1[2], lane & 28);

    const int b = bh >> 4;
    const int h = bh & 15;
    const float i00 = 1.f / l00, i01 = 1.f / l01;
    const float i10 = 1.f / l10, i11 = 1.f / l11;
    const int qrow = q0 + w * 32 + g;
#pragma unroll
    for (int j = 0; j < 8; j++) {
        const int col = h * 64 + j * 8 + 2 * t;
        *reinterpret_cast<uint32_t*>(&g_ctx[(size_t)(b * Sn + qrow) * Dn + col]) =
            pack_h2(O0[j][0] * i00, O0[j][1] * i00);
        *reinterpret_cast<uint32_t*>(&g_ctx[(size_t)(b * Sn + qrow + 8) * Dn + col]) =
            pack_h2(O0[j][2] * i01, O0[j][3] * i01);
        *reinterpret_cast<uint32_t*>(&g_ctx[(size_t)(b * Sn + qrow + 16) * Dn + col]) =
            pack_h2(O1[j][0] * i10, O1[j][1] * i10);
        *reinterpret_cast<uint32_t*>(&g_ctx[(size_t)(b * Sn + qrow + 24) * Dn + col]) =
            pack_h2(O1[j][2] * i11, O1[j][3] * i11);
    }
}

// ---------------------------------------------------------------------------
extern "C" void kernel_launch(void* const* d_in, const int* in_sizes, int n_in,
                              void* d_out, int out_size)
{
    (void)in_sizes; (void)n_in; (void)out_size;
    const float* x  = (const float*)d_in[0];
    const float* wq = (const float*)d_in[1];
    const float* wk = (const float*)d_in[2];
    const float* wv = (const float*)d_in[3];
    const float* wo = (const float*)d_in[4];
    float* out = (float*)d_out;

    cudaFuncSetAttribute(mma_gemm<0>, cudaFuncAttributeMaxDynamicSharedMemorySize, SMEM_BYTES);
    cudaFuncSetAttribute(mma_gemm<1>, cudaFuncAttributeMaxDynamicSharedMemorySize, SMEM_BYTES);
    cudaFuncSetAttribute(mma_gemm<2>, cudaFuncAttributeMaxDynamicSharedMemorySize, SMEM_BYTES);
    cudaFuncSetAttribute(flash_mma,   cudaFuncAttributeMaxDynamicSharedMemorySize, FLASH_SMEM);

    // Prepasses
    round_x_kernel<<<2048, 256>>>((const float4*)x);
    transpose_w_kernel<<<dim3(Dn / 32, Dn / 32, 4), dim3(32, 8)>>>(wq, wk, wv, wo);

    // 1) Q/K projections (fp16 tensor cores), BN=256
    mma_gemm<0><<<dim3(Dn / 256, MRn / 128, 2), 256, SMEM_BYTES>>>(nullptr);
    // 1b) V projection as swapped GEMM -> g_Vt directly (coalesced)
    mma_gemm<2><<<dim3(MRn / 256, Dn / 128, 1), 256, SMEM_BYTES>>>(nullptr);
    // 2) Causal flash attention (fp16 tensor cores), 256-query blocks
    flash_mma<<<dim3(Sn / 256, Bn * Hn), 256, FLASH_SMEM>>>();
    // 3) Output projection (fp16 tensor cores)
    mma_gemm<1><<<dim3(Dn / 256, MRn / 128, 1), 256, SMEM_BYTES>>>(out);
}

// round 12
// speedup vs baseline: 1.0517x; 1.0517x over previous
#include <cuda_runtime.h>
#include <cuda_fp16.h>
#include <cstdint>

// Problem constants
constexpr int Bn  = 4;
constexpr int Sn  = 2048;
constexpr int Dn  = 1024;
constexpr int Hn  = 16;
constexpr int HDn = 64;
constexpr int MRn = Bn * Sn;

constexpr unsigned PROJ_SMEM  = 147456 + 256;  // proj: 3 x (16KB A + 32KB B)
constexpr unsigned WO_SMEM    = 98304 + 256;   // wo:   3 x (16KB A + 16KB B)
constexpr unsigned FLASH_SMEM = 65536 + 256;   // flash: Q 16KB + K 3x8KB + Vt 3x8KB

// Scratch (device globals; 16B-aligned for cp.async)
__device__ __align__(256) __half g_Q[(size_t)Bn * Hn * Sn * HDn];   // [b,h,s,hd] (scaled log2e/8)
__device__ __align__(256) __half g_K[(size_t)Bn * Hn * Sn * HDn];
__device__ __align__(256) __half g_Vt[(size_t)Bn * Hn * HDn * Sn];  // [b,h,hd,s]
__device__ __align__(256) __half g_ctx[(size_t)MRn * Dn];           // [b,s,d]
__device__ __align__(256) __half g_x[(size_t)MRn * Dn];             // half copy of x
__device__ __align__(256) __half g_Wt[(size_t)4 * Dn * Dn];         // [z][n][k] transposed

// ---------------------------------------------------------------------------
// Helpers
// ---------------------------------------------------------------------------
__device__ __forceinline__ uint32_t smem_u32(const void* p) {
    uint32_t a;
    asm("{ .reg .u64 t; cvta.to.shared.u64 t, %1; cvt.u32.u64 %0, t; }" : "=r"(a) : "l"(p));
    return a;
}
__device__ __forceinline__ void cp16(uint32_t dst, const void* src) {
    asm volatile("cp.async.cg.shared.global [%0], [%1], 16;" :: "r"(dst), "l"(src) : "memory");
}
#define CP_COMMIT() asm volatile("cp.async.commit_group;" ::: "memory")
#define CP_WAIT1()  asm volatile("cp.async.wait_group 1;"  ::: "memory")

__device__ __forceinline__ void ldmx4(uint32_t* r, uint32_t a) {
    asm volatile("ldmatrix.sync.aligned.m8n8.x4.shared.b16 {%0,%1,%2,%3}, [%4];"
                 : "=r"(r[0]), "=r"(r[1]), "=r"(r[2]), "=r"(r[3]) : "r"(a));
}
__device__ __forceinline__ uint32_t pack_h2(float lo, float hi) {
    __half2 h = __floats2half2_rn(lo, hi);
    return *reinterpret_cast<uint32_t*>(&h);
}
__device__ __forceinline__ uint32_t ex2h2(uint32_t x) {
    uint32_t r;
    asm("ex2.approx.f16x2 %0, %1;" : "=r"(r) : "r"(x));
    return r;
}

// mma.sync m16n8k16 fp16 -> f32 accum: D = A@B + D (A row-major, B col-major)
__device__ __forceinline__ void mma_f16(float* c, const uint32_t* a, const uint32_t* b) {
    asm volatile(
        "mma.sync.aligned.m16n8k16.row.col.f32.f16.f16.f32 "
        "{%0,%1,%2,%3}, {%4,%5,%6,%7}, {%8,%9}, {%0,%1,%2,%3};"
        : "+f"(c[0]), "+f"(c[1]), "+f"(c[2]), "+f"(c[3])
        : "r"(a[0]), "r"(a[1]), "r"(a[2]), "r"(a[3]), "r"(b[0]), "r"(b[1]));
}

// ---------------------------------------------------------------------------
// Fused prepass: blocks [0,2048) round x -> g_x; blocks [2048,6144) transpose
// + round weights: g_Wt[z][n][k] = half(W_z[k][n]).
// ---------------------------------------------------------------------------
__global__ __launch_bounds__(256) void prepass_kernel(
    const float4* __restrict__ x,
    const float* __restrict__ w0, const float* __restrict__ w1,
    const float* __restrict__ w2, const float* __restrict__ w3)
{
    const int tid = threadIdx.x;
    if (blockIdx.x < 2048) {
        size_t n4 = (size_t)MRn * Dn / 4;
        for (size_t i = (size_t)blockIdx.x * 256 + tid; i < n4; i += (size_t)2048 * 256) {
            float4 v = x[i];
            reinterpret_cast<uint2*>(g_x)[i] =
                make_uint2(pack_h2(v.x, v.y), pack_h2(v.z, v.w));
        }
    } else {
        __shared__ float tile[32][33];
        const int bid = blockIdx.x - 2048;          // [0, 4096)
        const int z   = bid >> 10;
        const int rem = bid & 1023;
        const int bx  = rem & 31;
        const int byy = rem >> 5;
        const float* w = (z == 0) ? w0 : (z == 1) ? w1 : (z == 2) ? w2 : w3;
        __half* wt = g_Wt + (size_t)z * Dn * Dn;

        const int tx = tid & 31, ty = tid >> 5;     // 32 x 8
        const int n  = bx * 32 + tx;
        const int k0 = byy * 32;
#pragma unroll
        for (int j = 0; j < 32; j += 8)
            tile[ty + j][tx] = w[(size_t)(k0 + ty + j) * Dn + n];
        __syncthreads();
        const int ko = k0 + tx;
        const int no = bx * 32 + ty;
#pragma unroll
        for (int j = 0; j < 32; j += 8)
            wt[(size_t)(no + j) * Dn + ko] = __float2half_rn(tile[tx][ty + j]);
    }
}

// ---------------------------------------------------------------------------
// Fused projection GEMM: one launch, 768 CTAs, BM=128, BN=256, warp 64x64.
//   id <  512: QK. z = id>>8; bx = (id&255)&3 (Dn/256), by = (id&255)>>2 (MRn/128)
//              A=g_x[m], Bt=g_Wt[z][n] -> g_Q (scaled log2e/8) / g_K
//   id >= 512: Vt. bx = (id-512)&31 (MRn/256), by = (id-512)>>5 (Dn/128)
//              A=g_Wt[2][m], Bt=g_x[n] -> g_Vt [d][s] coalesced packed
// 3-stage cp.async, one sync per kt, BK=64 halves (128B rows, XOR swizzle).
// ---------------------------------------------------------------------------
__global__ __launch_bounds__(256)
void proj_fused()
{
    extern __shared__ char smem[];
    const uint32_t sbuf = (smem_u32(smem) + 127u) & ~127u;

    const int tid  = threadIdx.x;
    const int wid  = tid >> 5;
    const int lane = tid & 31;
    const int g    = lane >> 2;
    const int t    = lane & 3;
    const int wm   = wid & 1;
    const int wn   = wid >> 1;

    const int id = blockIdx.x;
    const bool isQK = (id < 512);
    int z, bx, by;
    if (isQK) { z = id >> 8; int r = id & 255; bx = r & 3;  by = r >> 2; }
    else      { z = 2;       int r = id - 512; bx = r & 31; by = r >> 5; }
    const int n0 = bx * 256;
    const int m0 = by * 128;

    const __half* __restrict__ A  = isQK ? g_x : (g_Wt + (size_t)2 * Dn * Dn);
    const __half* __restrict__ Bt = isQK ? (g_Wt + (size_t)z * Dn * Dn) : g_x;

    auto load_tiles = [&](int kt, int bufi) {
        const uint32_t dst = sbuf + (uint32_t)bufi * 49152u;
        const int k0 = kt * 64;
#pragma unroll
        for (int i = 0; i < 4; i++) {          // A: 128 rows
            int c  = tid + i * 256;
            int r  = c >> 3;
            int kc = c & 7;
            uint32_t off = (uint32_t)(r * 128) + (uint32_t)((kc ^ (r & 7)) << 4);
            cp16(dst + off, A + (size_t)(m0 + r) * Dn + k0 + kc * 8);
        }
#pragma unroll
        for (int i = 0; i < 8; i++) {          // B: 256 rows
            int c  = tid + i * 256;
            int r  = c >> 3;
            int kc = c & 7;
            uint32_t off = (uint32_t)(r * 128) + (uint32_t)((kc ^ (r & 7)) << 4);
            cp16(dst + 16384u + off, Bt + (size_t)(n0 + r) * Dn + k0 + kc * 8);
        }
    };

    load_tiles(0, 0); CP_COMMIT();
    load_tiles(1, 1); CP_COMMIT();

    float acc[4][8][4];
#pragma unroll
    for (int i = 0; i < 4; i++)
#pragma unroll
        for (int j = 0; j < 8; j++)
#pragma unroll
            for (int r = 0; r < 4; r++) acc[i][j][r] = 0.f;

    const uint32_t aRowL = (uint32_t)(wm * 64 + (lane & 15));
    const uint32_t aSw   = aRowL & 7u;
    const uint32_t aCs   = (uint32_t)(lane >> 4);
    const uint32_t bRowL = (uint32_t)(wn * 64 + (lane & 7));
    const uint32_t bSw   = bRowL & 7u;
    const uint32_t bCs   = (uint32_t)((lane >> 3) & 1);
    const uint32_t bJ    = (uint32_t)(lane >> 4);

    for (int kt = 0; kt < 16; kt++) {      // Dn / 64
        CP_WAIT1();
        __syncthreads();
        if (kt + 2 < 16) load_tiles(kt + 2, (kt + 2) % 3);
        CP_COMMIT();

        const uint32_t aB = sbuf + (uint32_t)(kt % 3) * 49152u;
        const uint32_t bB = aB + 16384u;

#pragma unroll
        for (int ks = 0; ks < 4; ks++) {   // 4 x k16
            uint32_t afr[4][4];
#pragma unroll
            for (int i = 0; i < 4; i++)
                ldmx4(afr[i], aB + (aRowL + (uint32_t)(i * 16)) * 128u
                                 + ((((uint32_t)(2 * ks) + aCs) ^ aSw) << 4));
            uint32_t bfr[8][2];
#pragma unroll
            for (int p = 0; p < 4; p++) {
                uint32_t tmp[4];
                ldmx4(tmp, bB + (bRowL + ((uint32_t)(p * 2) + bJ) * 8u) * 128u
                             + ((((uint32_t)(2 * ks) + bCs) ^ bSw) << 4));
                bfr[p * 2][0]     = tmp[0]; bfr[p * 2][1]     = tmp[1];
                bfr[p * 2 + 1][0] = tmp[2]; bfr[p * 2 + 1][1] = tmp[3];
            }
#pragma unroll
            for (int i = 0; i < 4; i++)
#pragma unroll
                for (int j = 0; j < 8; j++)
                    mma_f16(acc[i][j], afr[i], bfr[j]);
        }
    }

    // --------------------------- Epilogue ---------------------------
    if (!isQK) {
        // Vt: rows = d-dim (h,hd), cols = m-dim (b,s): coalesced packed writes
#pragma unroll
        for (int i = 0; i < 4; i++) {
            const int row0 = m0 + wm * 64 + i * 16 + g;
#pragma unroll
            for (int j = 0; j < 8; j++) {
                const int col = n0 + wn * 64 + j * 8 + 2 * t;   // m index (s even)
                const int b   = col >> 11;
                const int s   = col & 2047;
#pragma unroll
                for (int half = 0; half < 2; half++) {
                    const int d  = row0 + half * 8;
                    const int h  = d >> 6;
                    const int hd = d & 63;
                    *reinterpret_cast<uint32_t*>(
                        g_Vt + ((size_t)((b * Hn + h) * HDn + hd)) * Sn + s) =
                        pack_h2(acc[i][j][half * 2], acc[i][j][half * 2 + 1]);
                }
            }
        }
    } else {
        __half* outq = (z == 0) ? g_Q : g_K;
        const float sc = (z == 0) ? 0.18033688011112042f : 1.0f;  // log2e/8
#pragma unroll
        for (int i = 0; i < 4; i++) {
            const int row0 = m0 + wm * 64 + i * 16 + g;
#pragma unroll
            for (int j = 0; j < 8; j++) {
                const int col = n0 + wn * 64 + j * 8 + 2 * t;
                const int h   = col >> 6;
                const int hd  = col & 63;
#pragma unroll
                for (int half = 0; half < 2; half++) {
                    const int row = row0 + half * 8;
                    const int b   = row >> 11;
                    const int s   = row & 2047;
                    *reinterpret_cast<uint32_t*>(
                        outq + ((size_t)((b * Hn + h) * Sn + s)) * HDn + hd) =
                        pack_h2(acc[i][j][half * 2] * sc, acc[i][j][half * 2 + 1] * sc);
                }
            }
        }
    }
}

// ---------------------------------------------------------------------------
// Output projection GEMM (BN=128, R10 body): C = ctx @ wo -> fp32 out
// ---------------------------------------------------------------------------
__global__ __launch_bounds__(256)
void wo_gemm(float* __restrict__ Cout)
{
    extern __shared__ char smem[];
    const uint32_t sbuf = (smem_u32(smem) + 127u) & ~127u;

    const int tid  = threadIdx.x;
    const int wid  = tid >> 5;
    const int lane = tid & 31;
    const int g    = lane >> 2;
    const int t    = lane & 3;
    const int wm   = wid & 1;
    const int wn   = wid >> 1;

    const int n0 = blockIdx.x * 128;
    const int m0 = blockIdx.y * 128;

    const __half* __restrict__ A  = g_ctx;
    const __half* __restrict__ Bt = g_Wt + (size_t)3 * Dn * Dn;

    auto load_tiles = [&](int kt, int bufi) {
        const uint32_t dst = sbuf + (uint32_t)bufi * 32768u;
        const int k0 = kt * 64;
#pragma unroll
        for (int i = 0; i < 4; i++) {
            int c  = tid + i * 256;
            int r  = c >> 3;
            int kc = c & 7;
            uint32_t off = (uint32_t)(r * 128) + (uint32_t)((kc ^ (r & 7)) << 4);
            cp16(dst + off,           A  + (size_t)(m0 + r) * Dn + k0 + kc * 8);
            cp16(dst + 16384u + off,  Bt + (size_t)(n0 + r) * Dn + k0 + kc * 8);
        }
    };

    load_tiles(0, 0); CP_COMMIT();
    load_tiles(1, 1); CP_COMMIT();

    float acc[4][4][4];
#pragma unroll
    for (int i = 0; i < 4; i++)
#pragma unroll
        for (int j = 0; j < 4; j++)
#pragma unroll
            for (int r = 0; r < 4; r++) acc[i][j][r] = 0.f;

    const uint32_t aRowL = (uint32_t)(wm * 64 + (lane & 15));
    const uint32_t aSw   = aRowL & 7u;
    const uint32_t aCs   = (uint32_t)(lane >> 4);
    const uint32_t bRowL = (uint32_t)(wn * 32 + (lane & 7));
    const uint32_t bSw   = bRowL & 7u;
    const uint32_t bCs   = (uint32_t)((lane >> 3) & 1);
    const uint32_t bJ    = (uint32_t)(lane >> 4);

    for (int kt = 0; kt < 16; kt++) {
        CP_WAIT1();
        __syncthreads();
        if (kt + 2 < 16) load_tiles(kt + 2, (kt + 2) % 3);
        CP_COMMIT();

        const uint32_t aB = sbuf + (uint32_t)(kt % 3) * 32768u;
        const uint32_t bB = aB + 16384u;

#pragma unroll
        for (int ks = 0; ks < 4; ks++) {
            uint32_t afr[4][4];
#pragma unroll
            for (int i = 0; i < 4; i++)
                ldmx4(afr[i], aB + (aRowL + (uint32_t)(i * 16)) * 128u
                                 + ((((uint32_t)(2 * ks) + aCs) ^ aSw) << 4));
            uint32_t bfr[4][2];
#pragma unroll
            for (int p = 0; p < 2; p++) {
                uint32_t tmp[4];
                ldmx4(tmp, bB + (bRowL + ((uint32_t)(p * 2) + bJ) * 8u) * 128u
                             + ((((uint32_t)(2 * ks) + bCs) ^ bSw) << 4));
                bfr[p * 2][0]     = tmp[0]; bfr[p * 2][1]     = tmp[1];
                bfr[p * 2 + 1][0] = tmp[2]; bfr[p * 2 + 1][1] = tmp[3];
            }
#pragma unroll
            for (int i = 0; i < 4; i++)
#pragma unroll
                for (int j = 0; j < 4; j++)
                    mma_f16(acc[i][j], afr[i], bfr[j]);
        }
    }

#pragma unroll
    for (int i = 0; i < 4; i++) {
        const int row0 = m0 + wm * 64 + i * 16 + g;
#pragma unroll
        for (int j = 0; j < 4; j++) {
            const int col = n0 + wn * 32 + j * 8 + 2 * t;
#pragma unroll
            for (int half = 0; half < 2; half++) {
                const int row = row0 + half * 8;
                *reinterpret_cast<float2*>(Cout + (size_t)row * Dn + col) =
                    make_float2(acc[i][j][half * 2], acc[i][j][half * 2 + 1]);
            }
        }
    }
}

// ---------------------------------------------------------------------------
// Tensor-core flash attention (causal), fp16 MMA, no-max softmax (R10 body).
// Block: 128 queries x (b,h). 8 warps, warp = 16 query rows x 64 keys.
// ---------------------------------------------------------------------------
__global__ __launch_bounds__(256, 2)
void flash_mma()
{
    extern __shared__ char fsm[];
    const uint32_t sb = (smem_u32(fsm) + 127u) & ~127u;
    const uint32_t Qb = sb;            // 16KB
    const uint32_t Kb = sb + 16384u;   // 3 x 8KB
    const uint32_t Vb = sb + 40960u;   // 3 x 8KB

    const int qt = (int)gridDim.x - 1 - (int)blockIdx.x;   // heavy tiles first
    const int bh = blockIdx.y;
    const int q0 = qt * 128;

    const __half* __restrict__ Qg  = g_Q  + (size_t)bh * Sn * HDn;
    const __half* __restrict__ Kg  = g_K  + (size_t)bh * Sn * HDn;
    const __half* __restrict__ Vtg = g_Vt + (size_t)bh * HDn * Sn;

    const int tid  = threadIdx.x;
    const int w    = tid >> 5;
    const int lane = tid & 31;
    const int g    = lane >> 2;
    const int t    = lane & 3;

    auto loadKV = [&](int kt, int bufi) {
        const int k0 = kt * 64;
        const uint32_t kb = Kb + (uint32_t)bufi * 8192u;
        const uint32_t vb = Vb + (uint32_t)bufi * 8192u;
#pragma unroll
        for (int i = 0; i < 2; i++) {
            int lin = tid + i * 256;
            int r = lin >> 3, kc = lin & 7;
            uint32_t off = (uint32_t)(r * 128) + (uint32_t)((kc ^ (r & 7)) << 4);
            cp16(kb + off, Kg  + (size_t)(k0 + r) * HDn + kc * 8);
            cp16(vb + off, Vtg + (size_t)r * Sn + k0 + kc * 8);
        }
    };

#pragma unroll
    for (int i = 0; i < 4; i++) {
        int lin = tid + i * 256;
        int r = lin >> 3, kc = lin & 7;
        uint32_t dst = Qb + (uint32_t)(r * 128) + (uint32_t)((kc ^ (r & 7)) << 4);
        cp16(dst, Qg + (size_t)(q0 + r) * HDn + kc * 8);
    }
    loadKV(0, 0); CP_COMMIT();
    loadKV(1, 1); CP_COMMIT();

    float O[8][4];
#pragma unroll
    for (int j = 0; j < 8; j++)
#pragma unroll
        for (int r = 0; r < 4; r++) O[j][r] = 0.f;
    float lacc[4] = {0.f, 0.f, 0.f, 0.f};

    uint32_t qa[4][4];
    const int nk = 2 * qt + 2;

    const uint32_t bones = (lane < 4) ? 0x3C003C00u : 0u;
    const uint32_t bz[2] = {bones, bones};

    const uint32_t aRowL = (uint32_t)(w * 16 + (lane & 15));
    const uint32_t aSw   = (uint32_t)(lane & 7);
    const uint32_t aCs   = (uint32_t)(lane >> 4);
    const uint32_t bRowL = (uint32_t)((lane & 7) + (lane >> 4) * 8);
    const uint32_t bSw   = (uint32_t)(lane & 7);
    const uint32_t bCs   = (uint32_t)((lane >> 3) & 1);

    for (int kt = 0; kt < nk; kt++) {
        CP_WAIT1();
        __syncthreads();
        if (kt + 2 < nk) loadKV(kt + 2, (kt + 2) % 3);
        CP_COMMIT();

        if (kt == 0) {
#pragma unroll
            for (int ks = 0; ks < 4; ks++)
                ldmx4(qa[ks], Qb + aRowL * 128u
                                 + ((((uint32_t)(2 * ks) + aCs) ^ aSw) << 4));
        }

        const int k0 = kt * 64;
        const uint32_t kb = Kb + (uint32_t)(kt % 3) * 8192u;
        const uint32_t vb = Vb + (uint32_t)(kt % 3) * 8192u;

        float S[8][4];
#pragma unroll
        for (int j = 0; j < 8; j++)
#pragma unroll
            for (int r = 0; r < 4; r++) S[j][r] = 0.f;

#pragma unroll
        for (int ks = 0; ks < 4; ks++) {
            const uint32_t csw = (((uint32_t)(2 * ks) + bCs) ^ bSw) << 4;
#pragma unroll
            for (int p = 0; p < 4; p++) {
                uint32_t tmp[4];
                ldmx4(tmp, kb + (bRowL + (uint32_t)(p * 16)) * 128u + csw);
                mma_f16(S[p * 2],     qa[ks], tmp);
                mma_f16(S[p * 2 + 1], qa[ks], tmp + 2);
            }
        }

        const int qr0 = q0 + w * 16 + g;
        const int qr1 = qr0 + 8;
        if ((k0 + 63) > q0) {
#pragma unroll
            for (int j = 0; j < 8; j++) {
                const int key0 = k0 + j * 8 + 2 * t;
                const int key1 = key0 + 1;
                if (key0 > qr0) S[j][0] = -1e30f;
                if (key1 > qr0) S[j][1] = -1e30f;
                if (key0 > qr1) S[j][2] = -1e30f;
                if (key1 > qr1) S[j][3] = -1e30f;
            }
        }

#pragma unroll
        for (int ks = 0; ks < 4; ks++) {
            uint32_t a[4] = {
                ex2h2(pack_h2(S[2 * ks][0],     S[2 * ks][1])),
                ex2h2(pack_h2(S[2 * ks][2],     S[2 * ks][3])),
                ex2h2(pack_h2(S[2 * ks + 1][0], S[2 * ks + 1][1])),
                ex2h2(pack_h2(S[2 * ks + 1][2], S[2 * ks + 1][3])) };

            mma_f16(lacc, a, bz);

            const uint32_t csw = (((uint32_t)(2 * ks) + bCs) ^ bSw) << 4;
#pragma unroll
            for (int p = 0; p < 4; p++) {
                uint32_t tmp[4];
                ldmx4(tmp, vb + (bRowL + (uint32_t)(p * 16)) * 128u + csw);
                mma_f16(O[p * 2],     a, tmp);
                mma_f16(O[p * 2 + 1], a, tmp + 2);
            }
        }
    }

    const float l0 = __shfl_sync(0xffffffffu, lacc[0], lane & 28);
    const float l1 = __shfl_sync(0xffffffffu, lacc[2], lane & 28);

    const int b = bh >> 4;
    const int h = bh & 15;
    const float i0 = 1.f / l0;
    const float i1 = 1.f / l1;
    const int qrow = q0 + w * 16 + g;
#pragma unroll
    for (int j = 0; j < 8; j++) {
        const int col = h * 64 + j * 8 + 2 * t;
        *reinterpret_cast<uint32_t*>(&g_ctx[(size_t)(b * Sn + qrow) * Dn + col]) =
            pack_h2(O[j][0] * i0, O[j][1] * i0);
        *reinterpret_cast<uint32_t*>(&g_ctx[(size_t)(b * Sn + qrow + 8) * Dn + col]) =
            pack_h2(O[j][2] * i1, O[j][3] * i1);
    }
}

// ---------------------------------------------------------------------------
extern "C" void kernel_launch(void* const* d_in, const int* in_sizes, int n_in,
                              void* d_out, int out_size)
{
    (void)in_sizes; (void)n_in; (void)out_size;
    const float* x  = (const float*)d_in[0];
    const float* wq = (const float*)d_in[1];
    const float* wk = (const float*)d_in[2];
    const float* wv = (const float*)d_in[3];
    const float* wo = (const float*)d_in[4];
    float* out = (float*)d_out;

    cudaFuncSetAttribute(proj_fused, cudaFuncAttributeMaxDynamicSharedMemorySize, PROJ_SMEM);
    cudaFuncSetAttribute(wo_gemm,    cudaFuncAttributeMaxDynamicSharedMemorySize, WO_SMEM);
    cudaFuncSetAttribute(flash_mma,  cudaFuncAttributeMaxDynamicSharedMemorySize, FLASH_SMEM);

    // Prepass: x rounding + weight transposes in one launch
    prepass_kernel<<<6144, 256>>>((const float4*)x, wq, wk, wv, wo);

    // 1) Q/K/Vt projections fused into one 768-CTA launch (BN=256)
    proj_fused<<<768, 256, PROJ_SMEM>>>();
    // 2) Causal flash attention (fp16 tensor cores), 128-query blocks
    flash_mma<<<dim3(Sn / 128, Bn * Hn), 256, FLASH_SMEM>>>();
    // 3) Output projection
    wo_gemm<<<dim3(Dn / 128, MRn / 128), 256, WO_SMEM>>>(out);
}

// round 13
// speedup vs baseline: 1.1578x; 1.1008x over previous
#include <cuda_runtime.h>
#include <cuda_fp16.h>
#include <cstdint>

// Problem constants
constexpr int Bn  = 4;
constexpr int Sn  = 2048;
constexpr int Dn  = 1024;
constexpr int Hn  = 16;
constexpr int HDn = 64;
constexpr int MRn = Bn * Sn;

constexpr unsigned GEMM_SMEM  = 98304 + 256;   // 3 x (16KB A + 16KB B)
constexpr unsigned FLASH_SMEM = 65536 + 256;   // Q 16KB + K 3x8KB + Vt 3x8KB

// Scratch (device globals; 16B-aligned for cp.async)
__device__ __align__(256) __half g_Q[(size_t)Bn * Hn * Sn * HDn];   // [b,h,s,hd] (scaled log2e/8)
__device__ __align__(256) __half g_K[(size_t)Bn * Hn * Sn * HDn];
__device__ __align__(256) __half g_Vt[(size_t)Bn * Hn * HDn * Sn];  // [b,h,hd,s]
__device__ __align__(256) __half g_ctx[(size_t)MRn * Dn];           // [b,s,d]
__device__ __align__(256) __half g_x[(size_t)MRn * Dn];             // half copy of x
__device__ __align__(256) __half g_Wt[(size_t)4 * Dn * Dn];         // [z][n][k] transposed

// ---------------------------------------------------------------------------
// Helpers
// ---------------------------------------------------------------------------
__device__ __forceinline__ uint32_t smem_u32(const void* p) {
    uint32_t a;
    asm("{ .reg .u64 t; cvta.to.shared.u64 t, %1; cvt.u32.u64 %0, t; }" : "=r"(a) : "l"(p));
    return a;
}
__device__ __forceinline__ void cp16(uint32_t dst, const void* src) {
    asm volatile("cp.async.cg.shared.global [%0], [%1], 16;" :: "r"(dst), "l"(src) : "memory");
}
#define CP_COMMIT() asm volatile("cp.async.commit_group;" ::: "memory")
#define CP_WAIT1()  asm volatile("cp.async.wait_group 1;"  ::: "memory")

__device__ __forceinline__ void ldmx4(uint32_t* r, uint32_t a) {
    asm volatile("ldmatrix.sync.aligned.m8n8.x4.shared.b16 {%0,%1,%2,%3}, [%4];"
                 : "=r"(r[0]), "=r"(r[1]), "=r"(r[2]), "=r"(r[3]) : "r"(a));
}
__device__ __forceinline__ uint32_t pack_h2(float lo, float hi) {
    __half2 h = __floats2half2_rn(lo, hi);
    return *reinterpret_cast<uint32_t*>(&h);
}
__device__ __forceinline__ uint32_t ex2h2(uint32_t x) {
    uint32_t r;
    asm("ex2.approx.f16x2 %0, %1;" : "=r"(r) : "r"(x));
    return r;
}

// mma.sync m16n8k16 fp16 -> f32 accum: D = A@B + D (A row-major, B col-major)
__device__ __forceinline__ void mma_f16(float* c, const uint32_t* a, const uint32_t* b) {
    asm volatile(
        "mma.sync.aligned.m16n8k16.row.col.f32.f16.f16.f32 "
        "{%0,%1,%2,%3}, {%4,%5,%6,%7}, {%8,%9}, {%0,%1,%2,%3};"
        : "+f"(c[0]), "+f"(c[1]), "+f"(c[2]), "+f"(c[3])
        : "r"(a[0]), "r"(a[1]), "r"(a[2]), "r"(a[3]), "r"(b[0]), "r"(b[1]));
}

// ---------------------------------------------------------------------------
// Fused prepass: blocks [0,2048) round x -> g_x; blocks [2048,6144) transpose
// + round weights: g_Wt[z][n][k] = half(W_z[k][n]).
// ---------------------------------------------------------------------------
__global__ __launch_bounds__(256) void prepass_kernel(
    const float4* __restrict__ x,
    const float* __restrict__ w0, const float* __restrict__ w1,
    const float* __restrict__ w2, const float* __restrict__ w3)
{
    const int tid = threadIdx.x;
    if (blockIdx.x < 2048) {
        size_t n4 = (size_t)MRn * Dn / 4;
        for (size_t i = (size_t)blockIdx.x * 256 + tid; i < n4; i += (size_t)2048 * 256) {
            float4 v = x[i];
            reinterpret_cast<uint2*>(g_x)[i] =
                make_uint2(pack_h2(v.x, v.y), pack_h2(v.z, v.w));
        }
    } else {
        __shared__ float tile[32][33];
        const int bid = blockIdx.x - 2048;          // [0, 4096)
        const int z   = bid >> 10;
        const int rem = bid & 1023;
        const int bx  = rem & 31;
        const int byy = rem >> 5;
        const float* w = (z == 0) ? w0 : (z == 1) ? w1 : (z == 2) ? w2 : w3;
        __half* wt = g_Wt + (size_t)z * Dn * Dn;

        const int tx = tid & 31, ty = tid >> 5;     // 32 x 8
        const int n  = bx * 32 + tx;
        const int k0 = byy * 32;
#pragma unroll
        for (int j = 0; j < 32; j += 8)
            tile[ty + j][tx] = w[(size_t)(k0 + ty + j) * Dn + n];
        __syncthreads();
        const int ko = k0 + tx;
        const int no = bx * 32 + ty;
#pragma unroll
        for (int j = 0; j < 32; j += 8)
            wt[(size_t)(no + j) * Dn + ko] = __float2half_rn(tile[tx][ty + j]);
    }
}

// ===========================================================================
// GEMM core: 128 threads (4 warps, 2Mx2N), warp tile 64x64, BM=BN=128,
// BK=64 halves (128B rows, XOR swizzle), 3-stage cp.async, 1 sync/kt.
// Registers ~185 -> 2 CTAs/SM co-resident (phase overlap across CTAs).
// MODE 0: fused projections, flat grid: id<1024 QK (z=id>>9), id>=1024 Vt.
// MODE 1: wo: A=g_ctx, Bt=g_Wt[3] -> Cout fp32.
// ===========================================================================
template <int MODE>
__global__ __launch_bounds__(128, 2)
void mma_gemm(float* __restrict__ Cout)
{
    extern __shared__ char smem[];
    const uint32_t sbuf = (smem_u32(smem) + 127u) & ~127u;

    const int tid  = threadIdx.x;
    const int wid  = tid >> 5;
    const int lane = tid & 31;
    const int g    = lane >> 2;
    const int t    = lane & 3;
    const int wm   = wid & 1;     // 2 warps along M
    const int wn   = wid >> 1;    // 2 warps along N

    int z = 3, m0, n0;
    bool isVt = false;
    if (MODE == 0) {
        const int id = blockIdx.x;
        if (id < 1024) {          // QK: z in {0,1}, 8 n-tiles x 64 m-tiles
            z = id >> 9;
            const int r = id & 511;
            n0 = (r & 7) * 128;
            m0 = (r >> 3) * 128;
        } else {                  // Vt: A = Wt[2] (M=Dn), Bt = g_x (N=MRn)
            isVt = true;
            const int r = id - 1024;
            n0 = (r & 63) * 128;
            m0 = (r >> 6) * 128;
        }
    } else {
        n0 = blockIdx.x * 128;
        m0 = blockIdx.y * 128;
    }

    const __half* __restrict__ A =
        (MODE == 1) ? g_ctx : (isVt ? (g_Wt + (size_t)2 * Dn * Dn) : g_x);
    const __half* __restrict__ Bt =
        (MODE == 1) ? (g_Wt + (size_t)3 * Dn * Dn)
                    : (isVt ? g_x : (g_Wt + (size_t)z * Dn * Dn));

    auto load_tiles = [&](int kt, int bufi) {
        const uint32_t dst = sbuf + (uint32_t)bufi * 32768u;
        const int k0 = kt * 64;
#pragma unroll
        for (int i = 0; i < 8; i++) {          // A: 128 rows x 64 halves
            int c  = tid + i * 128;
            int r  = c >> 3;
            int kc = c & 7;
            uint32_t off = (uint32_t)(r * 128) + (uint32_t)((kc ^ (r & 7)) << 4);
            cp16(dst + off,           A  + (size_t)(m0 + r) * Dn + k0 + kc * 8);
            cp16(dst + 16384u + off,  Bt + (size_t)(n0 + r) * Dn + k0 + kc * 8);
        }
    };

    load_tiles(0, 0); CP_COMMIT();
    load_tiles(1, 1); CP_COMMIT();

    float acc[4][8][4];
#pragma unroll
    for (int i = 0; i < 4; i++)
#pragma unroll
        for (int j = 0; j < 8; j++)
#pragma unroll
            for (int r = 0; r < 4; r++) acc[i][j][r] = 0.f;

    // Per-lane ldmatrix address components
    const uint32_t aRowL = (uint32_t)(wm * 64 + (lane & 15));    // + i*16
    const uint32_t aSw   = aRowL & 7u;
    const uint32_t aCs   = (uint32_t)(lane >> 4);
    const uint32_t bRowL = (uint32_t)(wn * 64 + (lane & 7));     // + (p*2 + bJ)*8
    const uint32_t bSw   = bRowL & 7u;
    const uint32_t bCs   = (uint32_t)((lane >> 3) & 1);
    const uint32_t bJ    = (uint32_t)(lane >> 4);

    for (int kt = 0; kt < 16; kt++) {      // Dn / 64
        CP_WAIT1();
        __syncthreads();
        if (kt + 2 < 16) load_tiles(kt + 2, (kt + 2) % 3);
        CP_COMMIT();

        const uint32_t aB = sbuf + (uint32_t)(kt % 3) * 32768u;
        const uint32_t bB = aB + 16384u;

#pragma unroll
        for (int ks = 0; ks < 4; ks++) {   // 4 x k16
            uint32_t afr[4][4];
#pragma unroll
            for (int i = 0; i < 4; i++)
                ldmx4(afr[i], aB + (aRowL + (uint32_t)(i * 16)) * 128u
                                 + ((((uint32_t)(2 * ks) + aCs) ^ aSw) << 4));
            uint32_t bfr[8][2];
#pragma unroll
            for (int p = 0; p < 4; p++) {
                uint32_t tmp[4];
                ldmx4(tmp, bB + (bRowL + ((uint32_t)(p * 2) + bJ) * 8u) * 128u
                             + ((((uint32_t)(2 * ks) + bCs) ^ bSw) << 4));
                bfr[p * 2][0]     = tmp[0]; bfr[p * 2][1]     = tmp[1];
                bfr[p * 2 + 1][0] = tmp[2]; bfr[p * 2 + 1][1] = tmp[3];
            }
#pragma unroll
            for (int i = 0; i < 4; i++)
#pragma unroll
                for (int j = 0; j < 8; j++)
                    mma_f16(acc[i][j], afr[i], bfr[j]);
        }
    }

    // --------------------------- Epilogue ---------------------------
    if (MODE == 0 && isVt) {
        // rows = d-dim (h,hd), cols = m-dim (b,s): coalesced packed writes
#pragma unroll
        for (int i = 0; i < 4; i++) {
            const int row0 = m0 + wm * 64 + i * 16 + g;
#pragma unroll
            for (int j = 0; j < 8; j++) {
                const int col = n0 + wn * 64 + j * 8 + 2 * t;   // m index (s even)
                const int b   = col >> 11;
                const int s   = col & 2047;
#pragma unroll
                for (int half = 0; half < 2; half++) {
                    const int d  = row0 + half * 8;
                    const int h  = d >> 6;
                    const int hd = d & 63;
                    *reinterpret_cast<uint32_t*>(
                        g_Vt + ((size_t)((b * Hn + h) * HDn + hd)) * Sn + s) =
                        pack_h2(acc[i][j][half * 2], acc[i][j][half * 2 + 1]);
                }
            }
        }
    } else if (MODE == 0) {
        __half* outq = (z == 0) ? g_Q : g_K;
        const float sc = (z == 0) ? 0.18033688011112042f : 1.0f;  // log2e/8
#pragma unroll
        for (int i = 0; i < 4; i++) {
            const int row0 = m0 + wm * 64 + i * 16 + g;
#pragma unroll
            for (int j = 0; j < 8; j++) {
                const int col = n0 + wn * 64 + j * 8 + 2 * t;
                const int h   = col >> 6;
                const int hd  = col & 63;
#pragma unroll
                for (int half = 0; half < 2; half++) {
                    const int row = row0 + half * 8;
                    const int b   = row >> 11;
                    const int s   = row & 2047;
                    *reinterpret_cast<uint32_t*>(
                        outq + ((size_t)((b * Hn + h) * Sn + s)) * HDn + hd) =
                        pack_h2(acc[i][j][half * 2] * sc, acc[i][j][half * 2 + 1] * sc);
                }
            }
        }
    } else {
#pragma unroll
        for (int i = 0; i < 4; i++) {
            const int row0 = m0 + wm * 64 + i * 16 + g;
#pragma unroll
            for (int j = 0; j < 8; j++) {
                const int col = n0 + wn * 64 + j * 8 + 2 * t;
#pragma unroll
                for (int half = 0; half < 2; half++) {
                    const int row = row0 + half * 8;
                    *reinterpret_cast<float2*>(Cout + (size_t)row * Dn + col) =
                        make_float2(acc[i][j][half * 2], acc[i][j][half * 2 + 1]);
                }
            }
        }
    }
}

// ---------------------------------------------------------------------------
// Tensor-core flash attention (causal), fp16 MMA, no-max softmax (R10 body).
// Block: 128 queries x (b,h). 8 warps, warp = 16 query rows x 64 keys.
// ---------------------------------------------------------------------------
__global__ __launch_bounds__(256, 2)
void flash_mma()
{
    extern __shared__ char fsm[];
    const uint32_t sb = (smem_u32(fsm) + 127u) & ~127u;
    const uint32_t Qb = sb;            // 16KB
    const uint32_t Kb = sb + 16384u;   // 3 x 8KB
    const uint32_t Vb = sb + 40960u;   // 3 x 8KB

    const int qt = (int)gridDim.x - 1 - (int)blockIdx.x;   // heavy tiles first
    const int bh = blockIdx.y;
    const int q0 = qt * 128;

    const __half* __restrict__ Qg  = g_Q  + (size_t)bh * Sn * HDn;
    const __half* __restrict__ Kg  = g_K  + (size_t)bh * Sn * HDn;
    const __half* __restrict__ Vtg = g_Vt + (size_t)bh * HDn * Sn;

    const int tid  = threadIdx.x;
    const int w    = tid >> 5;
    const int lane = tid & 31;
    const int g    = lane >> 2;
    const int t    = lane & 3;

    auto loadKV = [&](int kt, int bufi) {
        const int k0 = kt * 64;
        const uint32_t kb = Kb + (uint32_t)bufi * 8192u;
        const uint32_t vb = Vb + (uint32_t)bufi * 8192u;
#pragma unroll
        for (int i = 0; i < 2; i++) {
            int lin = tid + i * 256;
            int r = lin >> 3, kc = lin & 7;
            uint32_t off = (uint32_t)(r * 128) + (uint32_t)((kc ^ (r & 7)) << 4);
            cp16(kb + off, Kg  + (size_t)(k0 + r) * HDn + kc * 8);
            cp16(vb + off, Vtg + (size_t)r * Sn + k0 + kc * 8);
        }
    };

#pragma unroll
    for (int i = 0; i < 4; i++) {
        int lin = tid + i * 256;
        int r = lin >> 3, kc = lin & 7;
        uint32_t dst = Qb + (uint32_t)(r * 128) + (uint32_t)((kc ^ (r & 7)) << 4);
        cp16(dst, Qg + (size_t)(q0 + r) * HDn + kc * 8);
    }
    loadKV(0, 0); CP_COMMIT();
    loadKV(1, 1); CP_COMMIT();

    float O[8][4];
#pragma unroll
    for (int j = 0; j < 8; j++)
#pragma unroll
        for (int r = 0; r < 4; r++) O[j][r] = 0.f;
    float lacc[4] = {0.f, 0.f, 0.f, 0.f};

    uint32_t qa[4][4];
    const int nk = 2 * qt + 2;

    const uint32_t bones = (lane < 4) ? 0x3C003C00u : 0u;
    const uint32_t bz[2] = {bones, bones};

    const uint32_t aRowL = (uint32_t)(w * 16 + (lane & 15));
    const uint32_t aSw   = (uint32_t)(lane & 7);
    const uint32_t aCs   = (uint32_t)(lane >> 4);
    const uint32_t bRowL = (uint32_t)((lane & 7) + (lane >> 4) * 8);
    const uint32_t bSw   = (uint32_t)(lane & 7);
    const uint32_t bCs   = (uint32_t)((lane >> 3) & 1);

    for (int kt = 0; kt < nk; kt++) {
        CP_WAIT1();
        __syncthreads();
        if (kt + 2 < nk) loadKV(kt + 2, (kt + 2) % 3);
        CP_COMMIT();

        if (kt == 0) {
#pragma unroll
            for (int ks = 0; ks < 4; ks++)
                ldmx4(qa[ks], Qb + aRowL * 128u
                                 + ((((uint32_t)(2 * ks) + aCs) ^ aSw) << 4));
        }

        const int k0 = kt * 64;
        const uint32_t kb = Kb + (uint32_t)(kt % 3) * 8192u;
        const uint32_t vb = Vb + (uint32_t)(kt % 3) * 8192u;

        float S[8][4];
#pragma unroll
        for (int j = 0; j < 8; j++)
#pragma unroll
            for (int r = 0; r < 4; r++) S[j][r] = 0.f;

#pragma unroll
        for (int ks = 0; ks < 4; ks++) {
            const uint32_t csw = (((uint32_t)(2 * ks) + bCs) ^ bSw) << 4;
#pragma unroll
            for (int p = 0; p < 4; p++) {
                uint32_t tmp[4];
                ldmx4(tmp, kb + (bRowL + (uint32_t)(p * 16)) * 128u + csw);
                mma_f16(S[p * 2],     qa[ks], tmp);
                mma_f16(S[p * 2 + 1], qa[ks], tmp + 2);
            }
        }

        const int qr0 = q0 + w * 16 + g;
        const int qr1 = qr0 + 8;
        if ((k0 + 63) > q0) {
#pragma unroll
            for (int j = 0; j < 8; j++) {
                const int key0 = k0 + j * 8 + 2 * t;
                const int key1 = key0 + 1;
                if (key0 > qr0) S[j][0] = -1e30f;
                if (key1 > qr0) S[j][1] = -1e30f;
                if (key0 > qr1) S[j][2] = -1e30f;
                if (key1 > qr1) S[j][3] = -1e30f;
            }
        }

#pragma unroll
        for (int ks = 0; ks < 4; ks++) {
            uint32_t a[4] = {
                ex2h2(pack_h2(S[2 * ks][0],     S[2 * ks][1])),
                ex2h2(pack_h2(S[2 * ks][2],     S[2 * ks][3])),
                ex2h2(pack_h2(S[2 * ks + 1][0], S[2 * ks + 1][1])),
                ex2h2(pack_h2(S[2 * ks + 1][2], S[2 * ks + 1][3])) };

            mma_f16(lacc, a, bz);

            const uint32_t csw = (((uint32_t)(2 * ks) + bCs) ^ bSw) << 4;
#pragma unroll
            for (int p = 0; p < 4; p++) {
                uint32_t tmp[4];
                ldmx4(tmp, vb + (bRowL + (uint32_t)(p * 16)) * 128u + csw);
                mma_f16(O[p * 2],     a, tmp);
                mma_f16(O[p * 2 + 1], a, tmp + 2);
            }
        }
    }

    const float l0 = __shfl_sync(0xffffffffu, lacc[0], lane & 28);
    const float l1 = __shfl_sync(0xffffffffu, lacc[2], lane & 28);

    const int b = bh >> 4;
    const int h = bh & 15;
    const float i0 = 1.f / l0;
    const float i1 = 1.f / l1;
    const int qrow = q0 + w * 16 + g;
#pragma unroll
    for (int j = 0; j < 8; j++) {
        const int col = h * 64 + j * 8 + 2 * t;
        *reinterpret_cast<uint32_t*>(&g_ctx[(size_t)(b * Sn + qrow) * Dn + col]) =
            pack_h2(O[j][0] * i0, O[j][1] * i0);
        *reinterpret_cast<uint32_t*>(&g_ctx[(size_t)(b * Sn + qrow + 8) * Dn + col]) =
            pack_h2(O[j][2] * i1, O[j][3] * i1);
    }
}

// ---------------------------------------------------------------------------
extern "C" void kernel_launch(void* const* d_in, const int* in_sizes, int n_in,
                              void* d_out, int out_size)
{
    (void)in_sizes; (void)n_in; (void)out_size;
    const float* x  = (const float*)d_in[0];
    const float* wq = (const float*)d_in[1];
    const float* wk = (const float*)d_in[2];
    const float* wv = (const float*)d_in[3];
    const float* wo = (const float*)d_in[4];
    float* out = (float*)d_out;

    cudaFuncSetAttribute(mma_gemm<0>, cudaFuncAttributeMaxDynamicSharedMemorySize, GEMM_SMEM);
    cudaFuncSetAttribute(mma_gemm<1>, cudaFuncAttributeMaxDynamicSharedMemorySize, GEMM_SMEM);
    cudaFuncSetAttribute(flash_mma,   cudaFuncAttributeMaxDynamicSharedMemorySize, FLASH_SMEM);

    // Prepass: x rounding + weight transposes in one launch
    prepass_kernel<<<6144, 256>>>((const float4*)x, wq, wk, wv, wo);

    // 1) Q/K/Vt projections fused: 1024 QK tiles + 512 Vt tiles, 128-thr CTAs
    mma_gemm<0><<<1536, 128, GEMM_SMEM>>>(nullptr);
    // 2) Causal flash attention (fp16 tensor cores), 128-query blocks
    flash_mma<<<dim3(Sn / 128, Bn * Hn), 256, FLASH_SMEM>>>();
    // 3) Output projection (128-thr CTAs, 64x64 warp tiles)
    mma_gemm<1><<<dim3(Dn / 128, MRn / 128), 128, GEMM_SMEM>>>(out);
}

// round 14
// speedup vs baseline: 1.1854x; 1.0239x over previous
#include <cuda_runtime.h>
#include <cuda_fp16.h>
#include <cstdint>

// Problem constants
constexpr int Bn  = 4;
constexpr int Sn  = 2048;
constexpr int Dn  = 1024;
constexpr int Hn  = 16;
constexpr int HDn = 64;
constexpr int MRn = Bn * Sn;

constexpr unsigned GEMM_SMEM  = 98304 + 256;   // 3 x (16KB A + 16KB B)
constexpr unsigned FLASH_SMEM = 65536 + 256;   // Q 16KB + K 3x8KB + Vt 3x8KB

// Scratch (device globals; 16B-aligned for cp.async)
__device__ __align__(256) __half g_Q[(size_t)Bn * Hn * Sn * HDn];   // [b,h,s,hd] (scaled log2e/8)
__device__ __align__(256) __half g_K[(size_t)Bn * Hn * Sn * HDn];
__device__ __align__(256) __half g_Vt[(size_t)Bn * Hn * HDn * Sn];  // [b,h,hd,s]
__device__ __align__(256) __half g_ctx[(size_t)MRn * Dn];           // [b,s,d]
__device__ __align__(256) __half g_x[(size_t)MRn * Dn];             // half copy of x
__device__ __align__(256) __half g_Wt[(size_t)4 * Dn * Dn];         // [z][n][k] transposed

// ---------------------------------------------------------------------------
// Helpers
// ---------------------------------------------------------------------------
__device__ __forceinline__ uint32_t smem_u32(const void* p) {
    uint32_t a;
    asm("{ .reg .u64 t; cvta.to.shared.u64 t, %1; cvt.u32.u64 %0, t; }" : "=r"(a) : "l"(p));
    return a;
}
__device__ __forceinline__ void cp16(uint32_t dst, const void* src) {
    asm volatile("cp.async.cg.shared.global [%0], [%1], 16;" :: "r"(dst), "l"(src) : "memory");
}
#define CP_COMMIT() asm volatile("cp.async.commit_group;" ::: "memory")
#define CP_WAIT1()  asm volatile("cp.async.wait_group 1;"  ::: "memory")

__device__ __forceinline__ void ldmx4(uint32_t* r, uint32_t a) {
    asm volatile("ldmatrix.sync.aligned.m8n8.x4.shared.b16 {%0,%1,%2,%3}, [%4];"
                 : "=r"(r[0]), "=r"(r[1]), "=r"(r[2]), "=r"(r[3]) : "r"(a));
}
__device__ __forceinline__ uint32_t pack_h2(float lo, float hi) {
    __half2 h = __floats2half2_rn(lo, hi);
    return *reinterpret_cast<uint32_t*>(&h);
}
__device__ __forceinline__ uint32_t ex2h2(uint32_t x) {
    uint32_t r;
    asm("ex2.approx.f16x2 %0, %1;" : "=r"(r) : "r"(x));
    return r;
}

// mma.sync m16n8k16 fp16 -> f32 accum: D = A@B + D (A row-major, B col-major)
__device__ __forceinline__ void mma_f16(float* c, const uint32_t* a, const uint32_t* b) {
    asm volatile(
        "mma.sync.aligned.m16n8k16.row.col.f32.f16.f16.f32 "
        "{%0,%1,%2,%3}, {%4,%5,%6,%7}, {%8,%9}, {%0,%1,%2,%3};"
        : "+f"(c[0]), "+f"(c[1]), "+f"(c[2]), "+f"(c[3])
        : "r"(a[0]), "r"(a[1]), "r"(a[2]), "r"(a[3]), "r"(b[0]), "r"(b[1]));
}

// ---------------------------------------------------------------------------
// Fused prepass: blocks [0,2048) round x -> g_x; blocks [2048,6144) transpose
// + round weights: g_Wt[z][n][k] = half(W_z[k][n]).
// ---------------------------------------------------------------------------
__global__ __launch_bounds__(256) void prepass_kernel(
    const float4* __restrict__ x,
    const float* __restrict__ w0, const float* __restrict__ w1,
    const float* __restrict__ w2, const float* __restrict__ w3)
{
    const int tid = threadIdx.x;
    if (blockIdx.x < 2048) {
        size_t n4 = (size_t)MRn * Dn / 4;
        for (size_t i = (size_t)blockIdx.x * 256 + tid; i < n4; i += (size_t)2048 * 256) {
            float4 v = x[i];
            reinterpret_cast<uint2*>(g_x)[i] =
                make_uint2(pack_h2(v.x, v.y), pack_h2(v.z, v.w));
        }
    } else {
        __shared__ float tile[32][33];
        const int bid = blockIdx.x - 2048;          // [0, 4096)
        const int z   = bid >> 10;
        const int rem = bid & 1023;
        const int bx  = rem & 31;
        const int byy = rem >> 5;
        const float* w = (z == 0) ? w0 : (z == 1) ? w1 : (z == 2) ? w2 : w3;
        __half* wt = g_Wt + (size_t)z * Dn * Dn;

        const int tx = tid & 31, ty = tid >> 5;     // 32 x 8
        const int n  = bx * 32 + tx;
        const int k0 = byy * 32;
#pragma unroll
        for (int j = 0; j < 32; j += 8)
            tile[ty + j][tx] = w[(size_t)(k0 + ty + j) * Dn + n];
        __syncthreads();
        const int ko = k0 + tx;
        const int no = bx * 32 + ty;
#pragma unroll
        for (int j = 0; j < 32; j += 8)
            wt[(size_t)(no + j) * Dn + ko] = __float2half_rn(tile[tx][ty + j]);
    }
}

// ===========================================================================
// GEMM core (R13): 128 threads (4 warps, 2Mx2N), warp tile 64x64, BM=BN=128,
// BK=64 halves (128B rows, XOR swizzle), 3-stage cp.async, 1 sync/kt.
// MODE 0: fused projections, flat grid: id<1024 QK (z=id>>9), id>=1024 Vt.
// MODE 1: wo: A=g_ctx, Bt=g_Wt[3] -> Cout fp32.
// ===========================================================================
template <int MODE>
__global__ __launch_bounds__(128, 2)
void mma_gemm(float* __restrict__ Cout)
{
    extern __shared__ char smem[];
    const uint32_t sbuf = (smem_u32(smem) + 127u) & ~127u;

    const int tid  = threadIdx.x;
    const int wid  = tid >> 5;
    const int lane = tid & 31;
    const int g    = lane >> 2;
    const int t    = lane & 3;
    const int wm   = wid & 1;
    const int wn   = wid >> 1;

    int z = 3, m0, n0;
    bool isVt = false;
    if (MODE == 0) {
        const int id = blockIdx.x;
        if (id < 1024) {
            z = id >> 9;
            const int r = id & 511;
            n0 = (r & 7) * 128;
            m0 = (r >> 3) * 128;
        } else {
            isVt = true;
            const int r = id - 1024;
            n0 = (r & 63) * 128;
            m0 = (r >> 6) * 128;
        }
    } else {
        n0 = blockIdx.x * 128;
        m0 = blockIdx.y * 128;
    }

    const __half* __restrict__ A =
        (MODE == 1) ? g_ctx : (isVt ? (g_Wt + (size_t)2 * Dn * Dn) : g_x);
    const __half* __restrict__ Bt =
        (MODE == 1) ? (g_Wt + (size_t)3 * Dn * Dn)
                    : (isVt ? g_x : (g_Wt + (size_t)z * Dn * Dn));

    auto load_tiles = [&](int kt, int bufi) {
        const uint32_t dst = sbuf + (uint32_t)bufi * 32768u;
        const int k0 = kt * 64;
#pragma unroll
        for (int i = 0; i < 8; i++) {
            int c  = tid + i * 128;
            int r  = c >> 3;
            int kc = c & 7;
            uint32_t off = (uint32_t)(r * 128) + (uint32_t)((kc ^ (r & 7)) << 4);
            cp16(dst + off,           A  + (size_t)(m0 + r) * Dn + k0 + kc * 8);
            cp16(dst + 16384u + off,  Bt + (size_t)(n0 + r) * Dn + k0 + kc * 8);
        }
    };

    load_tiles(0, 0); CP_COMMIT();
    load_tiles(1, 1); CP_COMMIT();

    float acc[4][8][4];
#pragma unroll
    for (int i = 0; i < 4; i++)
#pragma unroll
        for (int j = 0; j < 8; j++)
#pragma unroll
            for (int r = 0; r < 4; r++) acc[i][j][r] = 0.f;

    const uint32_t aRowL = (uint32_t)(wm * 64 + (lane & 15));
    const uint32_t aSw   = aRowL & 7u;
    const uint32_t aCs   = (uint32_t)(lane >> 4);
    const uint32_t bRowL = (uint32_t)(wn * 64 + (lane & 7));
    const uint32_t bSw   = bRowL & 7u;
    const uint32_t bCs   = (uint32_t)((lane >> 3) & 1);
    const uint32_t bJ    = (uint32_t)(lane >> 4);

    for (int kt = 0; kt < 16; kt++) {
        CP_WAIT1();
        __syncthreads();
        if (kt + 2 < 16) load_tiles(kt + 2, (kt + 2) % 3);
        CP_COMMIT();

        const uint32_t aB = sbuf + (uint32_t)(kt % 3) * 32768u;
        const uint32_t bB = aB + 16384u;

#pragma unroll
        for (int ks = 0; ks < 4; ks++) {
            uint32_t afr[4][4];
#pragma unroll
            for (int i = 0; i < 4; i++)
                ldmx4(afr[i], aB + (aRowL + (uint32_t)(i * 16)) * 128u
                                 + ((((uint32_t)(2 * ks) + aCs) ^ aSw) << 4));
            uint32_t bfr[8][2];
#pragma unroll
            for (int p = 0; p < 4; p++) {
                uint32_t tmp[4];
                ldmx4(tmp, bB + (bRowL + ((uint32_t)(p * 2) + bJ) * 8u) * 128u
                             + ((((uint32_t)(2 * ks) + bCs) ^ bSw) << 4));
                bfr[p * 2][0]     = tmp[0]; bfr[p * 2][1]     = tmp[1];
                bfr[p * 2 + 1][0] = tmp[2]; bfr[p * 2 + 1][1] = tmp[3];
            }
#pragma unroll
            for (int i = 0; i < 4; i++)
#pragma unroll
                for (int j = 0; j < 8; j++)
                    mma_f16(acc[i][j], afr[i], bfr[j]);
        }
    }

    // --------------------------- Epilogue ---------------------------
    if (MODE == 0 && isVt) {
#pragma unroll
        for (int i = 0; i < 4; i++) {
            const int row0 = m0 + wm * 64 + i * 16 + g;
#pragma unroll
            for (int j = 0; j < 8; j++) {
                const int col = n0 + wn * 64 + j * 8 + 2 * t;
                const int b   = col >> 11;
                const int s   = col & 2047;
#pragma unroll
                for (int half = 0; half < 2; half++) {
                    const int d  = row0 + half * 8;
                    const int h  = d >> 6;
                    const int hd = d & 63;
                    *reinterpret_cast<uint32_t*>(
                        g_Vt + ((size_t)((b * Hn + h) * HDn + hd)) * Sn + s) =
                        pack_h2(acc[i][j][half * 2], acc[i][j][half * 2 + 1]);
                }
            }
        }
    } else if (MODE == 0) {
        __half* outq = (z == 0) ? g_Q : g_K;
        const float sc = (z == 0) ? 0.18033688011112042f : 1.0f;  // log2e/8
#pragma unroll
        for (int i = 0; i < 4; i++) {
            const int row0 = m0 + wm * 64 + i * 16 + g;
#pragma unroll
            for (int j = 0; j < 8; j++) {
                const int col = n0 + wn * 64 + j * 8 + 2 * t;
                const int h   = col >> 6;
                const int hd  = col & 63;
#pragma unroll
                for (int half = 0; half < 2; half++) {
                    const int row = row0 + half * 8;
                    const int b   = row >> 11;
                    const int s   = row & 2047;
                    *reinterpret_cast<uint32_t*>(
                        outq + ((size_t)((b * Hn + h) * Sn + s)) * HDn + hd) =
                        pack_h2(acc[i][j][half * 2] * sc, acc[i][j][half * 2 + 1] * sc);
                }
            }
        }
    } else {
#pragma unroll
        for (int i = 0; i < 4; i++) {
            const int row0 = m0 + wm * 64 + i * 16 + g;
#pragma unroll
            for (int j = 0; j < 8; j++) {
                const int col = n0 + wn * 64 + j * 8 + 2 * t;
#pragma unroll
                for (int half = 0; half < 2; half++) {
                    const int row = row0 + half * 8;
                    *reinterpret_cast<float2*>(Cout + (size_t)row * Dn + col) =
                        make_float2(acc[i][j][half * 2], acc[i][j][half * 2 + 1]);
                }
            }
        }
    }
}

// ---------------------------------------------------------------------------
// Tensor-core flash attention (causal), fp16 MMA, no-max softmax.
// 128 threads (4 warps). Warp = 32 query rows (two m16 bands) x 64 keys:
// each K/V fragment read feeds BOTH bands -> half the fragment bytes per MMA.
// Block = 128 queries (grid unchanged). launch_bounds(128,2): 256-reg budget,
// 2 CTAs/SM. p = ex2.f16x2; row-sums via ones-column MMA; 3-stage cp.async.
// ---------------------------------------------------------------------------
__global__ __launch_bounds__(128, 2)
void flash_mma()
{
    extern __shared__ char fsm[];
    const uint32_t sb = (smem_u32(fsm) + 127u) & ~127u;
    const uint32_t Qb = sb;            // 16KB (128 rows x 64 halves)
    const uint32_t Kb = sb + 16384u;   // 3 x 8KB
    const uint32_t Vb = sb + 40960u;   // 3 x 8KB

    const int qt = (int)gridDim.x - 1 - (int)blockIdx.x;   // heavy tiles first
    const int bh = blockIdx.y;
    const int q0 = qt * 128;

    const __half* __restrict__ Qg  = g_Q  + (size_t)bh * Sn * HDn;
    const __half* __restrict__ Kg  = g_K  + (size_t)bh * Sn * HDn;
    const __half* __restrict__ Vtg = g_Vt + (size_t)bh * HDn * Sn;

    const int tid  = threadIdx.x;
    const int w    = tid >> 5;       // 0..3
    const int lane = tid & 31;
    const int g    = lane >> 2;
    const int t    = lane & 3;

    auto loadKV = [&](int kt, int bufi) {
        const int k0 = kt * 64;
        const uint32_t kb = Kb + (uint32_t)bufi * 8192u;
        const uint32_t vb = Vb + (uint32_t)bufi * 8192u;
#pragma unroll
        for (int i = 0; i < 4; i++) {
            int lin = tid + i * 128;             // 0..511
            int r = lin >> 3, kc = lin & 7;
            uint32_t off = (uint32_t)(r * 128) + (uint32_t)((kc ^ (r & 7)) << 4);
            cp16(kb + off, Kg  + (size_t)(k0 + r) * HDn + kc * 8);
            cp16(vb + off, Vtg + (size_t)r * Sn + k0 + kc * 8);
        }
    };

    // Prologue: Q tile (128 rows) + KV(0) in group 0; KV(1) in group 1
#pragma unroll
    for (int i = 0; i < 8; i++) {
        int lin = tid + i * 128;                 // 0..1023
        int r = lin >> 3, kc = lin & 7;
        uint32_t dst = Qb + (uint32_t)(r * 128) + (uint32_t)((kc ^ (r & 7)) << 4);
        cp16(dst, Qg + (size_t)(q0 + r) * HDn + kc * 8);
    }
    loadKV(0, 0); CP_COMMIT();
    loadKV(1, 1); CP_COMMIT();

    float O0[8][4], O1[8][4];
#pragma unroll
    for (int j = 0; j < 8; j++)
#pragma unroll
        for (int r = 0; r < 4; r++) { O0[j][r] = 0.f; O1[j][r] = 0.f; }
    float lacc0[4] = {0.f, 0.f, 0.f, 0.f};
    float lacc1[4] = {0.f, 0.f, 0.f, 0.f};

    uint32_t qa0[4][4], qa1[4][4];
    const int nk = 2 * qt + 2;

    const uint32_t bones = (lane < 4) ? 0x3C003C00u : 0u;
    const uint32_t bz[2] = {bones, bones};

    // Per-lane ldmatrix address components
    const uint32_t aRowL = (uint32_t)(w * 32 + (lane & 15));     // band0; band1 +16
    const uint32_t aSw   = (uint32_t)(lane & 7);
    const uint32_t aCs   = (uint32_t)(lane >> 4);
    const uint32_t bRowL = (uint32_t)((lane & 7) + (lane >> 4) * 8);  // + p*16
    const uint32_t bSw   = (uint32_t)(lane & 7);
    const uint32_t bCs   = (uint32_t)((lane >> 3) & 1);

    for (int kt = 0; kt < nk; kt++) {
        CP_WAIT1();
        __syncthreads();
        if (kt + 2 < nk) loadKV(kt + 2, (kt + 2) % 3);
        CP_COMMIT();

        if (kt == 0) {   // preload Q fragments for both bands
#pragma unroll
            for (int ks = 0; ks < 4; ks++) {
                const uint32_t csw = (((uint32_t)(2 * ks) + aCs) ^ aSw) << 4;
                ldmx4(qa0[ks], Qb + aRowL * 128u + csw);
                ldmx4(qa1[ks], Qb + (aRowL + 16u) * 128u + csw);
            }
        }

        const int k0 = kt * 64;
        const uint32_t kb = Kb + (uint32_t)(kt % 3) * 8192u;
        const uint32_t vb = Vb + (uint32_t)(kt % 3) * 8192u;

        // ---- S = Q @ K^T, both bands share each K fragment ----
        float S0[8][4], S1[8][4];
#pragma unroll
        for (int j = 0; j < 8; j++)
#pragma unroll
            for (int r = 0; r < 4; r++) { S0[j][r] = 0.f; S1[j][r] = 0.f; }

#pragma unroll
        for (int ks = 0; ks < 4; ks++) {
            const uint32_t csw = (((uint32_t)(2 * ks) + bCs) ^ bSw) << 4;
#pragma unroll
            for (int p = 0; p < 4; p++) {
                uint32_t tmp[4];
                ldmx4(tmp, kb + (bRowL + (uint32_t)(p * 16)) * 128u + csw);
                mma_f16(S0[p * 2],     qa0[ks], tmp);
                mma_f16(S0[p * 2 + 1], qa0[ks], tmp + 2);
                mma_f16(S1[p * 2],     qa1[ks], tmp);
                mma_f16(S1[p * 2 + 1], qa1[ks], tmp + 2);
            }
        }

        // ---- causal mask (tiles overlapping this warp's rows) ----
        const int qb0 = q0 + w * 32 + g;        // band0 rows qb0, qb0+8
        const int qb1 = qb0 + 16;               // band1 rows qb1, qb1+8
        if ((k0 + 63) > qb0) {
#pragma unroll
            for (int j = 0; j < 8; j++) {
                const int key0 = k0 + j * 8 + 2 * t;
                const int key1 = key0 + 1;
                if (key0 > qb0)     S0[j][0] = -1e30f;
                if (key1 > qb0)     S0[j][1] = -1e30f;
                if (key0 > qb0 + 8) S0[j][2] = -1e30f;
                if (key1 > qb0 + 8) S0[j][3] = -1e30f;
                if (key0 > qb1)     S1[j][0] = -1e30f;
                if (key1 > qb1)     S1[j][1] = -1e30f;
                if (key0 > qb1 + 8) S1[j][2] = -1e30f;
                if (key1 > qb1 + 8) S1[j][3] = -1e30f;
            }
        }

        // ---- p = 2^S; ctx += P @ V (V frag shared by bands); l via ones ----
#pragma unroll
        for (int ks = 0; ks < 4; ks++) {
            uint32_t a0[4] = {
                ex2h2(pack_h2(S0[2 * ks][0],     S0[2 * ks][1])),
                ex2h2(pack_h2(S0[2 * ks][2],     S0[2 * ks][3])),
                ex2h2(pack_h2(S0[2 * ks + 1][0], S0[2 * ks + 1][1])),
                ex2h2(pack_h2(S0[2 * ks + 1][2], S0[2 * ks + 1][3])) };
            uint32_t a1[4] = {
                ex2h2(pack_h2(S1[2 * ks][0],     S1[2 * ks][1])),
                ex2h2(pack_h2(S1[2 * ks][2],     S1[2 * ks][3])),
                ex2h2(pack_h2(S1[2 * ks + 1][0], S1[2 * ks + 1][1])),
                ex2h2(pack_h2(S1[2 * ks + 1][2], S1[2 * ks + 1][3])) };

            mma_f16(lacc0, a0, bz);
            mma_f16(lacc1, a1, bz);

            const uint32_t csw = (((uint32_t)(2 * ks) + bCs) ^ bSw) << 4;
#pragma unroll
            for (int p = 0; p < 4; p++) {
                uint32_t tmp[4];
                ldmx4(tmp, vb + (bRowL + (uint32_t)(p * 16)) * 128u + csw);
                mma_f16(O0[p * 2],     a0, tmp);
                mma_f16(O0[p * 2 + 1], a0, tmp + 2);
                mma_f16(O1[p * 2],     a1, tmp);
                mma_f16(O1[p * 2 + 1], a1, tmp + 2);
            }
        }
    }

    // ---- epilogue: broadcast l (col 0, lanes t==0), then ctx/l ----
    const float l00 = __shfl_sync(0xffffffffu, lacc0[0], lane & 28);
    const float l01 = __shfl_sync(0xffffffffu, lacc0[2], lane & 28);
    const float l10 = __shfl_sync(0xffffffffu, lacc1[0], lane & 28);
    const float l11 = __shfl_sync(0xffffffffu, lacc1[2], lane & 28);

    const int b = bh >> 4;
    const int h = bh & 15;
    const float i00 = 1.f / l00, i01 = 1.f / l01;
    const float i10 = 1.f / l10, i11 = 1.f / l11;
    const int qrow = q0 + w * 32 + g;
#pragma unroll
    for (int j = 0; j < 8; j++) {
        const int col = h * 64 + j * 8 + 2 * t;
        *reinterpret_cast<uint32_t*>(&g_ctx[(size_t)(b * Sn + qrow) * Dn + col]) =
            pack_h2(O0[j][0] * i00, O0[j][1] * i00);
        *reinterpret_cast<uint32_t*>(&g_ctx[(size_t)(b * Sn + qrow + 8) * Dn + col]) =
            pack_h2(O0[j][2] * i01, O0[j][3] * i01);
        *reinterpret_cast<uint32_t*>(&g_ctx[(size_t)(b * Sn + qrow + 16) * Dn + col]) =
            pack_h2(O1[j][0] * i10, O1[j][1] * i10);
        *reinterpret_cast<uint32_t*>(&g_ctx[(size_t)(b * Sn + qrow + 24) * Dn + col]) =
            pack_h2(O1[j][2] * i11, O1[j][3] * i11);
    }
}

// ---------------------------------------------------------------------------
extern "C" void kernel_launch(void* const* d_in, const int* in_sizes, int n_in,
                              void* d_out, int out_size)
{
    (void)in_sizes; (void)n_in; (void)out_size;
    const float* x  = (const float*)d_in[0];
    const float* wq = (const float*)d_in[1];
    const float* wk = (const float*)d_in[2];
    const float* wv = (const float*)d_in[3];
    const float* wo = (const float*)d_in[4];
    float* out = (float*)d_out;

    cudaFuncSetAttribute(mma_gemm<0>, cudaFuncAttributeMaxDynamicSharedMemorySize, GEMM_SMEM);
    cudaFuncSetAttribute(mma_gemm<1>, cudaFuncAttributeMaxDynamicSharedMemorySize, GEMM_SMEM);
    cudaFuncSetAttribute(flash_mma,   cudaFuncAttributeMaxDynamicSharedMemorySize, FLASH_SMEM);

    // Prepass: x rounding + weight transposes in one launch
    prepass_kernel<<<6144, 256>>>((const float4*)x, wq, wk, wv, wo);

    // 1) Q/K/Vt projections fused: 1024 QK tiles + 512 Vt tiles, 128-thr CTAs
    mma_gemm<0><<<1536, 128, GEMM_SMEM>>>(nullptr);
    // 2) Causal flash attention: 128-q blocks, 4 warps x 32 q-rows
    flash_mma<<<dim3(Sn / 128, Bn * Hn), 128, FLASH_SMEM>>>();
    // 3) Output projection (128-thr CTAs, 64x64 warp tiles)
    mma_gemm<1><<<dim3(Dn / 128, MRn / 128), 128, GEMM_SMEM>>>(out);
}

// round 16
// speedup vs baseline: 1.1964x; 1.0092x over previous
#include <cuda_runtime.h>
#include <cuda_fp16.h>
#include <cstdint>

// Problem constants
constexpr int Bn  = 4;
constexpr int Sn  = 2048;
constexpr int Dn  = 1024;
constexpr int Hn  = 16;
constexpr int HDn = 64;
constexpr int MRn = Bn * Sn;

constexpr unsigned GEMM_SMEM  = 98304 + 256;   // 3 x (16KB A + 16KB B)
constexpr unsigned FLASH_SMEM = 98304 + 256;   // 3 x 32KB stage regions (R0 overlays Q)

// Scratch (device globals; 16B-aligned for cp.async)
__device__ __align__(256) __half g_Q[(size_t)Bn * Hn * Sn * HDn];   // [b,h,s,hd] (scaled log2e/8)
__device__ __align__(256) __half g_K[(size_t)Bn * Hn * Sn * HDn];
__device__ __align__(256) __half g_Vt[(size_t)Bn * Hn * HDn * Sn];  // [b,h,hd,s]
__device__ __align__(256) __half g_ctx[(size_t)MRn * Dn];           // [b,s,d]
__device__ __align__(256) __half g_x[(size_t)MRn * Dn];             // half copy of x
__device__ __align__(256) __half g_Wt[(size_t)4 * Dn * Dn];         // [z][n][k] transposed

// ---------------------------------------------------------------------------
// Helpers
// ---------------------------------------------------------------------------
__device__ __forceinline__ uint32_t smem_u32(const void* p) {
    uint32_t a;
    asm("{ .reg .u64 t; cvta.to.shared.u64 t, %1; cvt.u32.u64 %0, t; }" : "=r"(a) : "l"(p));
    return a;
}
__device__ __forceinline__ void cp16(uint32_t dst, const void* src) {
    asm volatile("cp.async.cg.shared.global [%0], [%1], 16;" :: "r"(dst), "l"(src) : "memory");
}
#define CP_COMMIT() asm volatile("cp.async.commit_group;" ::: "memory")
#define CP_WAIT1()  asm volatile("cp.async.wait_group 1;"  ::: "memory")

__device__ __forceinline__ void ldmx4(uint32_t* r, uint32_t a) {
    asm volatile("ldmatrix.sync.aligned.m8n8.x4.shared.b16 {%0,%1,%2,%3}, [%4];"
                 : "=r"(r[0]), "=r"(r[1]), "=r"(r[2]), "=r"(r[3]) : "r"(a));
}
__device__ __forceinline__ uint32_t pack_h2(float lo, float hi) {
    __half2 h = __floats2half2_rn(lo, hi);
    return *reinterpret_cast<uint32_t*>(&h);
}
__device__ __forceinline__ uint32_t ex2h2(uint32_t x) {
    uint32_t r;
    asm("ex2.approx.f16x2 %0, %1;" : "=r"(r) : "r"(x));
    return r;
}

// mma.sync m16n8k16 fp16 -> f32 accum: D = A@B + D (A row-major, B col-major)
__device__ __forceinline__ void mma_f16(float* c, const uint32_t* a, const uint32_t* b) {
    asm volatile(
        "mma.sync.aligned.m16n8k16.row.col.f32.f16.f16.f32 "
        "{%0,%1,%2,%3}, {%4,%5,%6,%7}, {%8,%9}, {%0,%1,%2,%3};"
        : "+f"(c[0]), "+f"(c[1]), "+f"(c[2]), "+f"(c[3])
        : "r"(a[0]), "r"(a[1]), "r"(a[2]), "r"(a[3]), "r"(b[0]), "r"(b[1]));
}

// ---------------------------------------------------------------------------
// Fused prepass: blocks [0,2048) round x -> g_x; blocks [2048,6144) transpose
// + round weights: g_Wt[z][n][k] = half(W_z[k][n]).
// ---------------------------------------------------------------------------
__global__ __launch_bounds__(256) void prepass_kernel(
    const float4* __restrict__ x,
    const float* __restrict__ w0, const float* __restrict__ w1,
    const float* __restrict__ w2, const float* __restrict__ w3)
{
    const int tid = threadIdx.x;
    if (blockIdx.x < 2048) {
        size_t n4 = (size_t)MRn * Dn / 4;
        for (size_t i = (size_t)blockIdx.x * 256 + tid; i < n4; i += (size_t)2048 * 256) {
            float4 v = x[i];
            reinterpret_cast<uint2*>(g_x)[i] =
                make_uint2(pack_h2(v.x, v.y), pack_h2(v.z, v.w));
        }
    } else {
        __shared__ float tile[32][33];
        const int bid = blockIdx.x - 2048;          // [0, 4096)
        const int z   = bid >> 10;
        const int rem = bid & 1023;
        const int bx  = rem & 31;
        const int byy = rem >> 5;
        const float* w = (z == 0) ? w0 : (z == 1) ? w1 : (z == 2) ? w2 : w3;
        __half* wt = g_Wt + (size_t)z * Dn * Dn;

        const int tx = tid & 31, ty = tid >> 5;     // 32 x 8
        const int n  = bx * 32 + tx;
        const int k0 = byy * 32;
#pragma unroll
        for (int j = 0; j < 32; j += 8)
            tile[ty + j][tx] = w[(size_t)(k0 + ty + j) * Dn + n];
        __syncthreads();
        const int ko = k0 + tx;
        const int no = bx * 32 + ty;
#pragma unroll
        for (int j = 0; j < 32; j += 8)
            wt[(size_t)(no + j) * Dn + ko] = __float2half_rn(tile[tx][ty + j]);
    }
}

// ===========================================================================
// GEMM core (R13/R14): 128 threads (4 warps, 2Mx2N), warp tile 64x64,
// BM=BN=128, BK=64 halves (128B rows, XOR swizzle), 3-stage cp.async.
// MODE 0: fused projections, flat grid: id<1024 QK (z=id>>9), id>=1024 Vt.
// MODE 1: wo: A=g_ctx, Bt=g_Wt[3] -> Cout fp32.
// ===========================================================================
template <int MODE>
__global__ __launch_bounds__(128, 2)
void mma_gemm(float* __restrict__ Cout)
{
    extern __shared__ char smem[];
    const uint32_t sbuf = (smem_u32(smem) + 127u) & ~127u;

    const int tid  = threadIdx.x;
    const int wid  = tid >> 5;
    const int lane = tid & 31;
    const int g    = lane >> 2;
    const int t    = lane & 3;
    const int wm   = wid & 1;
    const int wn   = wid >> 1;

    int z = 3, m0, n0;
    bool isVt = false;
    if (MODE == 0) {
        const int id = blockIdx.x;
        if (id < 1024) {
            z = id >> 9;
            const int r = id & 511;
            n0 = (r & 7) * 128;
            m0 = (r >> 3) * 128;
        } else {
            isVt = true;
            const int r = id - 1024;
            n0 = (r & 63) * 128;
            m0 = (r >> 6) * 128;
        }
    } else {
        n0 = blockIdx.x * 128;
        m0 = blockIdx.y * 128;
    }

    const __half* __restrict__ A =
        (MODE == 1) ? g_ctx : (isVt ? (g_Wt + (size_t)2 * Dn * Dn) : g_x);
    const __half* __restrict__ Bt =
        (MODE == 1) ? (g_Wt + (size_t)3 * Dn * Dn)
                    : (isVt ? g_x : (g_Wt + (size_t)z * Dn * Dn));

    auto load_tiles = [&](int kt, int bufi) {
        const uint32_t dst = sbuf + (uint32_t)bufi * 32768u;
        const int k0 = kt * 64;
#pragma unroll
        for (int i = 0; i < 8; i++) {
            int c  = tid + i * 128;
            int r  = c >> 3;
            int kc = c & 7;
            uint32_t off = (uint32_t)(r * 128) + (uint32_t)((kc ^ (r & 7)) << 4);
            cp16(dst + off,           A  + (size_t)(m0 + r) * Dn + k0 + kc * 8);
            cp16(dst + 16384u + off,  Bt + (size_t)(n0 + r) * Dn + k0 + kc * 8);
        }
    };

    load_tiles(0, 0); CP_COMMIT();
    load_tiles(1, 1); CP_COMMIT();

    float acc[4][8][4];
#pragma unroll
    for (int i = 0; i < 4; i++)
#pragma unroll
        for (int j = 0; j < 8; j++)
#pragma unroll
            for (int r = 0; r < 4; r++) acc[i][j][r] = 0.f;

    const uint32_t aRowL = (uint32_t)(wm * 64 + (lane & 15));
    const uint32_t aSw   = aRowL & 7u;
    const uint32_t aCs   = (uint32_t)(lane >> 4);
    const uint32_t bRowL = (uint32_t)(wn * 64 + (lane & 7));
    const uint32_t bSw   = bRowL & 7u;
    const uint32_t bCs   = (uint32_t)((lane >> 3) & 1);
    const uint32_t bJ    = (uint32_t)(lane >> 4);

    for (int kt = 0; kt < 16; kt++) {
        CP_WAIT1();
        __syncthreads();
        if (kt + 2 < 16) load_tiles(kt + 2, (kt + 2) % 3);
        CP_COMMIT();

        const uint32_t aB = sbuf + (uint32_t)(kt % 3) * 32768u;
        const uint32_t bB = aB + 16384u;

#pragma unroll
        for (int ks = 0; ks < 4; ks++) {
            uint32_t afr[4][4];
#pragma unroll
            for (int i = 0; i < 4; i++)
                ldmx4(afr[i], aB + (aRowL + (uint32_t)(i * 16)) * 128u
                                 + ((((uint32_t)(2 * ks) + aCs) ^ aSw) << 4));
            uint32_t bfr[8][2];
#pragma unroll
            for (int p = 0; p < 4; p++) {
                uint32_t tmp[4];
                ldmx4(tmp, bB + (bRowL + ((uint32_t)(p * 2) + bJ) * 8u) * 128u
                             + ((((uint32_t)(2 * ks) + bCs) ^ bSw) << 4));
                bfr[p * 2][0]     = tmp[0]; bfr[p * 2][1]     = tmp[1];
                bfr[p * 2 + 1][0] = tmp[2]; bfr[p * 2 + 1][1] = tmp[3];
            }
#pragma unroll
            for (int i = 0; i < 4; i++)
#pragma unroll
                for (int j = 0; j < 8; j++)
                    mma_f16(acc[i][j], afr[i], bfr[j]);
        }
    }

    // --------------------------- Epilogue ---------------------------
    if (MODE == 0 && isVt) {
#pragma unroll
        for (int i = 0; i < 4; i++) {
            const int row0 = m0 + wm * 64 + i * 16 + g;
#pragma unroll
            for (int j = 0; j < 8; j++) {
                const int col = n0 + wn * 64 + j * 8 + 2 * t;
                const int b   = col >> 11;
                const int s   = col & 2047;
#pragma unroll
                for (int half = 0; half < 2; half++) {
                    const int d  = row0 + half * 8;
                    const int h  = d >> 6;
                    const int hd = d & 63;
                    *reinterpret_cast<uint32_t*>(
                        g_Vt + ((size_t)((b * Hn + h) * HDn + hd)) * Sn + s) =
                        pack_h2(acc[i][j][half * 2], acc[i][j][half * 2 + 1]);
                }
            }
        }
    } else if (MODE == 0) {
        __half* outq = (z == 0) ? g_Q : g_K;
        const float sc = (z == 0) ? 0.18033688011112042f : 1.0f;  // log2e/8
#pragma unroll
        for (int i = 0; i < 4; i++) {
            const int row0 = m0 + wm * 64 + i * 16 + g;
#pragma unroll
            for (int j = 0; j < 8; j++) {
                const int col = n0 + wn * 64 + j * 8 + 2 * t;
                const int h   = col >> 6;
                const int hd  = col & 63;
#pragma unroll
                for (int half = 0; half < 2; half++) {
                    const int row = row0 + half * 8;
                    const int b   = row >> 11;
                    const int s   = row & 2047;
                    *reinterpret_cast<uint32_t*>(
                        outq + ((size_t)((b * Hn + h) * Sn + s)) * HDn + hd) =
                        pack_h2(acc[i][j][half * 2] * sc, acc[i][j][half * 2 + 1] * sc);
                }
            }
        }
    } else {
#pragma unroll
        for (int i = 0; i < 4; i++) {
            const int row0 = m0 + wm * 64 + i * 16 + g;
#pragma unroll
            for (int j = 0; j < 8; j++) {
                const int col = n0 + wn * 64 + j * 8 + 2 * t;
#pragma unroll
                for (int half = 0; half < 2; half++) {
                    const int row = row0 + half * 8;
                    *reinterpret_cast<float2*>(Cout + (size_t)row * Dn + col) =
                        make_float2(acc[i][j][half * 2], acc[i][j][half * 2 + 1]);
                }
            }
        }
    }
}

// ---------------------------------------------------------------------------
// Tensor-core flash attention (causal), fp16 MMA, no-max softmax.
// 128 threads (4 warps), warp = 32 q-rows (two m16 bands) x 64 keys.
// 128-key pipeline stages (two 64-key panels per stage -> HALF the barriers),
// THREE 32KB stage regions rotating; region 0 overlays the Q tile (Q is dead
// after its fragments are preloaded, protected by a dedicated barrier).
// Stage s lives in region (s+1)%3; prefetch s+2 is 2 regions away -> no clash.
// p = ex2.f16x2; row-sums via ones-column MMA. Numerics identical to R14.
// ---------------------------------------------------------------------------
__global__ __launch_bounds__(128, 2)
void flash_mma()
{
    extern __shared__ char fsm[];
    const uint32_t sb = (smem_u32(fsm) + 127u) & ~127u;
    const uint32_t Qb = sb;                       // Q: first 16KB of region 0

    const int qt = (int)gridDim.x - 1 - (int)blockIdx.x;   // heavy tiles first
    const int bh = blockIdx.y;
    const int q0 = qt * 128;

    const __half* __restrict__ Qg  = g_Q  + (size_t)bh * Sn * HDn;
    const __half* __restrict__ Kg  = g_K  + (size_t)bh * Sn * HDn;
    const __half* __restrict__ Vtg = g_Vt + (size_t)bh * HDn * Sn;

    const int tid  = threadIdx.x;
    const int w    = tid >> 5;       // 0..3
    const int lane = tid & 31;
    const int g    = lane >> 2;
    const int t    = lane & 3;

    // Load one 128-key stage (two 64-key K panels + two V panels) into region.
    auto loadKV = [&](int s, int region) {
        const int k0 = s * 128;
        const uint32_t kb = sb + (uint32_t)region * 32768u;        // K: 2 x 8KB
        const uint32_t vb = kb + 16384u;                           // V: 2 x 8KB
#pragma unroll
        for (int i = 0; i < 8; i++) {
            int lin = tid + i * 128;             // 0..1023
            int r128 = lin >> 3, kc = lin & 7;
            int p = r128 >> 6, r = r128 & 63;
            uint32_t off = (uint32_t)(p * 8192) + (uint32_t)(r * 128)
                         + (uint32_t)((kc ^ (r & 7)) << 4);
            cp16(kb + off, Kg  + (size_t)(k0 + p * 64 + r) * HDn + kc * 8);
            cp16(vb + off, Vtg + (size_t)r * Sn + k0 + p * 64 + kc * 8);
        }
    };

    const int nk2 = qt + 1;    // 128-key stages

    // Prologue: group0 = Q tile + stage0 (region 1); group1 = stage1 (region 2)
#pragma unroll
    for (int i = 0; i < 8; i++) {
        int lin = tid + i * 128;
        int r = lin >> 3, kc = lin & 7;
        uint32_t dst = Qb + (uint32_t)(r * 128) + (uint32_t)((kc ^ (r & 7)) << 4);
        cp16(dst, Qg + (size_t)(q0 + r) * HDn + kc * 8);
    }
    loadKV(0, 1); CP_COMMIT();
    if (nk2 > 1) loadKV(1, 2);
    CP_COMMIT();

    // Per-lane ldmatrix address components
    const uint32_t aRowL = (uint32_t)(w * 32 + (lane & 15));     // band0; band1 +16
    const uint32_t aSw   = (uint32_t)(lane & 7);
    const uint32_t aCs   = (uint32_t)(lane >> 4);
    const uint32_t bRowL = (uint32_t)((lane & 7) + (lane >> 4) * 8);  // + p*16
    const uint32_t bSw   = (uint32_t)(lane & 7);
    const uint32_t bCs   = (uint32_t)((lane >> 3) & 1);

    // Wait for Q + stage0; preload Q fragments; then region 0 is reusable.
    CP_WAIT1();
    __syncthreads();
    uint32_t qa0[4][4], qa1[4][4];
#pragma unroll
    for (int ks = 0; ks < 4; ks++) {
        const uint32_t csw = (((uint32_t)(2 * ks) + aCs) ^ aSw) << 4;
        ldmx4(qa0[ks], Qb + aRowL * 128u + csw);
        ldmx4(qa1[ks], Qb + (aRowL + 16u) * 128u + csw);
    }
    __syncthreads();   // all Q reads done before stage2 cp.async writes region 0

    float O0[8][4], O1[8][4];
#pragma unroll
    for (int j = 0; j < 8; j++)
#pragma unroll
        for (int r = 0; r < 4; r++) { O0[j][r] = 0.f; O1[j][r] = 0.f; }
    float lacc0[4] = {0.f, 0.f, 0.f, 0.f};
    float lacc1[4] = {0.f, 0.f, 0.f, 0.f};

    const uint32_t bones = (lane < 4) ? 0x3C003C00u : 0u;
    const uint32_t bz[2] = {bones, bones};

    for (int kt2 = 0; kt2 < nk2; kt2++) {
        if (kt2 > 0) {       // stage kt2 completion (stage0 already waited above)
            CP_WAIT1();
            __syncthreads();
        }
        if (kt2 + 2 < nk2) loadKV(kt2 + 2, (kt2 + 3) % 3);
        CP_COMMIT();         // uniform group count

        const uint32_t region = sb + (uint32_t)((kt2 + 1) % 3) * 32768u;

        // Two 64-key panels per stage (no barrier between them)
#pragma unroll
        for (int half = 0; half < 2; half++) {
            const int k0 = kt2 * 128 + half * 64;
            const uint32_t kb = region + (uint32_t)(half * 8192);
            const uint32_t vb = region + 16384u + (uint32_t)(half * 8192);

            // ---- S = Q @ K^T, both bands share each K fragment ----
            float S0[8][4], S1[8][4];
#pragma unroll
            for (int j = 0; j < 8; j++)
#pragma unroll
                for (int r = 0; r < 4; r++) { S0[j][r] = 0.f; S1[j][r] = 0.f; }

#pragma unroll
            for (int ks = 0; ks < 4; ks++) {
                const uint32_t csw = (((uint32_t)(2 * ks) + bCs) ^ bSw) << 4;
#pragma unroll
                for (int p = 0; p < 4; p++) {
                    uint32_t tmp[4];
                    ldmx4(tmp, kb + (bRowL + (uint32_t)(p * 16)) * 128u + csw);
                    mma_f16(S0[p * 2],     qa0[ks], tmp);
                    mma_f16(S0[p * 2 + 1], qa0[ks], tmp + 2);
                    mma_f16(S1[p * 2],     qa1[ks], tmp);
                    mma_f16(S1[p * 2 + 1], qa1[ks], tmp + 2);
                }
            }

            // ---- causal mask (panels overlapping this warp's rows) ----
            const int qb0 = q0 + w * 32 + g;        // band0 rows qb0, qb0+8
            const int qb1 = qb0 + 16;               // band1 rows qb1, qb1+8
            if ((k0 + 63) > qb0) {
#pragma unroll
                for (int j = 0; j < 8; j++) {
                    const int key0 = k0 + j * 8 + 2 * t;
                    const int key1 = key0 + 1;
                    if (key0 > qb0)     S0[j][0] = -1e30f;
                    if (key1 > qb0)     S0[j][1] = -1e30f;
                    if (key0 > qb0 + 8) S0[j][2] = -1e30f;
                    if (key1 > qb0 + 8) S0[j][3] = -1e30f;
                    if (key0 > qb1)     S1[j][0] = -1e30f;
                    if (key1 > qb1)     S1[j][1] = -1e30f;
                    if (key0 > qb1 + 8) S1[j][2] = -1e30f;
                    if (key1 > qb1 + 8) S1[j][3] = -1e30f;
                }
            }

            // ---- p = 2^S; ctx += P @ V (V frag shared by bands); l ones-MMA ----
#pragma unroll
            for (int ks = 0; ks < 4; ks++) {
                uint32_t a0[4] = {
                    ex2h2(pack_h2(S0[2 * ks][0],     S0[2 * ks][1])),
                    ex2h2(pack_h2(S0[2 * ks][2],     S0[2 * ks][3])),
                    ex2h2(pack_h2(S0[2 * ks + 1][0], S0[2 * ks + 1][1])),
                    ex2h2(pack_h2(S0[2 * ks + 1][2], S0[2 * ks + 1][3])) };
                uint32_t a1[4] = {
                    ex2h2(pack_h2(S1[2 * ks][0],     S1[2 * ks][1])),
                    ex2h2(pack_h2(S1[2 * ks][2],     S1[2 * ks][3])),
                    ex2h2(pack_h2(S1[2 * ks + 1][0], S1[2 * ks + 1][1])),
                    ex2h2(pack_h2(S1[2 * ks + 1][2], S1[2 * ks + 1][3])) };

                mma_f16(lacc0, a0, bz);
                mma_f16(lacc1, a1, bz);

                const uint32_t csw = (((uint32_t)(2 * ks) + bCs) ^ bSw) << 4;
#pragma unroll
                for (int p = 0; p < 4; p++) {
                    uint32_t tmp[4];
                    ldmx4(tmp, vb + (bRowL + (uint32_t)(p * 16)) * 128u + csw);
                    mma_f16(O0[p * 2],     a0, tmp);
                    mma_f16(O0[p * 2 + 1], a0, tmp + 2);
                    mma_f16(O1[p * 2],     a1, tmp);
                    mma_f16(O1[p * 2 + 1], a1, tmp + 2);
                }
            }
        }
    }

    // ---- epilogue: broadcast l (col 0, lanes t==0), then ctx/l ----
    const float l00 = __shfl_sync(0xffffffffu, lacc0[0], lane & 28);
    const float l01 = __shfl_sync(0xffffffffu, lacc0[2], lane & 28);
    const float l10 = __shfl_sync(0xffffffffu, lacc1[0], lane & 28);
    const float l11 = __shfl_sync(0xffffffffu, lacc1[2], lane & 28);

    const int b = bh >> 4;
    const int h = bh & 15;
    const float i00 = 1.f / l00, i01 = 1.f / l01;
    const float i10 = 1.f / l10, i11 = 1.f / l11;
    const int qrow = q0 + w * 32 + g;
#pragma unroll
    for (int j = 0; j < 8; j++) {
        const int col = h * 64 + j * 8 + 2 * t;
        *reinterpret_cast<uint32_t*>(&g_ctx[(size_t)(b * Sn + qrow) * Dn + col]) =
            pack_h2(O0[j][0] * i00, O0[j][1] * i00);
        *reinterpret_cast<uint32_t*>(&g_ctx[(size_t)(b * Sn + qrow + 8) * Dn + col]) =
            pack_h2(O0[j][2] * i01, O0[j][3] * i01);
        *reinterpret_cast<uint32_t*>(&g_ctx[(size_t)(b * Sn + qrow + 16) * Dn + col]) =
            pack_h2(O1[j][0] * i10, O1[j][1] * i10);
        *reinterpret_cast<uint32_t*>(&g_ctx[(size_t)(b * Sn + qrow + 24) * Dn + col]) =
            pack_h2(O1[j][2] * i11, O1[j][3] * i11);
    }
}

// ---------------------------------------------------------------------------
extern "C" void kernel_launch(void* const* d_in, const int* in_sizes, int n_in,
                              void* d_out, int out_size)
{
    (void)in_sizes; (void)n_in; (void)out_size;
    const float* x  = (const float*)d_in[0];
    const float* wq = (const float*)d_in[1];
    const float* wk = (const float*)d_in[2];
    const float* wv = (const float*)d_in[3];
    const float* wo = (const float*)d_in[4];
    float* out = (float*)d_out;

    cudaFuncSetAttribute(mma_gemm<0>, cudaFuncAttributeMaxDynamicSharedMemorySize, GEMM_SMEM);
    cudaFuncSetAttribute(mma_gemm<1>, cudaFuncAttributeMaxDynamicSharedMemorySize, GEMM_SMEM);
    cudaFuncSetAttribute(flash_mma,   cudaFuncAttributeMaxDynamicSharedMemorySize, FLASH_SMEM);

    // Prepass: x rounding + weight transposes in one launch
    prepass_kernel<<<6144, 256>>>((const float4*)x, wq, wk, wv, wo);

    // 1) Q/K/Vt projections fused: 1024 QK tiles + 512 Vt tiles, 128-thr CTAs
    mma_gemm<0><<<1536, 128, GEMM_SMEM>>>(nullptr);
    // 2) Causal flash attention: 128-q blocks, 4 warps x 32 q-rows, 128-key stages
    flash_mma<<<dim3(Sn / 128, Bn * Hn), 128, FLASH_SMEM>>>();
    // 3) Output projection (128-thr CTAs, 64x64 warp tiles)
    mma_gemm<1><<<dim3(Dn / 128, MRn / 128), 128, GEMM_SMEM>>>(out);
}